// round 10
// baseline (speedup 1.0000x reference)
#include <cuda_runtime.h>
#include <cuda_bf16.h>
#include <cstdint>

#define SEQC 2048
#define BATCHC 4
#define NHEAD 16
#define DMOD 1024
#define MTOT (BATCHC * SEQC)     // 8192
#define QSZ (MTOT * DMOD)        // 8388608 elems per Q/K/V tensor (B*H*S*64)

__device__ __nv_bfloat16 g_xh[MTOT * DMOD], g_xl[MTOT * DMOD];
__device__ __nv_bfloat16 g_wh[4 * DMOD * DMOD], g_wl[4 * DMOD * DMOD];
__device__ __nv_bfloat16 g_qkvh[3 * QSZ], g_qkvl[3 * QSZ];
__device__ __nv_bfloat16 g_aoh[MTOT * DMOD], g_aol[MTOT * DMOD];

// ------------------------------ helpers -------------------------------------
__device__ __forceinline__ uint32_t su32(const void* p) {
    uint32_t a;
    asm("{ .reg .u64 t; cvta.to.shared.u64 t, %1; cvt.u32.u64 %0, t; }" : "=r"(a) : "l"(p));
    return a;
}
__device__ __forceinline__ uint32_t pk2(float e0, float e1) {
    uint32_t d;
    asm("cvt.rn.bf16x2.f32 %0, %1, %2;" : "=r"(d) : "f"(e1), "f"(e0));
    return d;
}
__device__ __forceinline__ void split2(float a, float b, uint32_t& h, uint32_t& l) {
    float ha = __bfloat162float(__float2bfloat16(a));
    float hb = __bfloat162float(__float2bfloat16(b));
    h = pk2(ha, hb);
    l = pk2(a - ha, b - hb);
}
__device__ __forceinline__ void ldsm4(uint32_t& r0, uint32_t& r1, uint32_t& r2,
                                      uint32_t& r3, uint32_t a) {
    asm volatile("ldmatrix.sync.aligned.m8n8.x4.shared.b16 {%0,%1,%2,%3}, [%4];"
                 : "=r"(r0), "=r"(r1), "=r"(r2), "=r"(r3) : "r"(a));
}
__device__ __forceinline__ void ldsm4t(uint32_t& r0, uint32_t& r1, uint32_t& r2,
                                       uint32_t& r3, uint32_t a) {
    asm volatile("ldmatrix.sync.aligned.m8n8.x4.trans.shared.b16 {%0,%1,%2,%3}, [%4];"
                 : "=r"(r0), "=r"(r1), "=r"(r2), "=r"(r3) : "r"(a));
}
__device__ __forceinline__ void mmabf(float* c, const uint32_t* a, const uint32_t* b) {
    asm volatile(
        "mma.sync.aligned.m16n8k16.row.col.f32.bf16.bf16.f32 "
        "{%0,%1,%2,%3},{%4,%5,%6,%7},{%8,%9},{%0,%1,%2,%3};"
        : "+f"(c[0]), "+f"(c[1]), "+f"(c[2]), "+f"(c[3])
        : "r"(a[0]), "r"(a[1]), "r"(a[2]), "r"(a[3]), "r"(b[0]), "r"(b[1]));
}
#define CP_ASYNC(dst, src) \
    asm volatile("cp.async.ca.shared.global [%0], [%1], 16;" :: "r"(dst), "l"(src) : "memory")
#define CP_COMMIT() asm volatile("cp.async.commit_group;" ::: "memory")
#define CP_WAIT(n)  asm volatile("cp.async.wait_group %0;" :: "n"(n) : "memory")

// ------------------------- fp32 -> bf16 hi/lo split --------------------------
__global__ void split_k(const float4* __restrict__ s, uint2* __restrict__ hi,
                        uint2* __restrict__ lo, int n4) {
    int i = blockIdx.x * blockDim.x + threadIdx.x;
    if (i >= n4) return;
    float4 v = s[i];
    uint32_t h0, l0, h1, l1;
    split2(v.x, v.y, h0, l0);
    split2(v.z, v.w, h1, l1);
    hi[i] = make_uint2(h0, h1);
    lo[i] = make_uint2(l0, l1);
}

// ---------- GEMM: C[M,N] = A[M,1024] B[N,1024]^T, bf16x3 (R9-verbatim) -------
#define GPB 80
#define ARR (128 * GPB)
#define BUF (4 * ARR)

template <int MODE>                  // 1: split-QKV bf16 out, 0: fp32 out
__global__ __launch_bounds__(256, 2) void gemm_bf(const __nv_bfloat16* __restrict__ Ah,
                                                  const __nv_bfloat16* __restrict__ Al,
                                                  const __nv_bfloat16* __restrict__ Bh,
                                                  const __nv_bfloat16* __restrict__ Bl,
                                                  float* __restrict__ C,
                                                  uint32_t* __restrict__ Oh,
                                                  uint32_t* __restrict__ Ol) {
    extern __shared__ char sm[];
    const uint32_t sb = su32(sm);
    const int tid = threadIdx.x, lane = tid & 31, wid = tid >> 5;
    const int m0 = blockIdx.y * 128, n0 = blockIdx.x * 128;
    const int wm = (wid >> 2) * 64, wn = (wid & 3) * 32;

    auto fill = [&](int kb, int buf) {
        uint32_t base = sb + buf * BUF;
#pragma unroll
        for (int i = 0; i < 2; i++) {
            int idx = tid + i * 256;
            int row = idx >> 2, c4 = idx & 3;
            uint32_t off = (uint32_t)row * GPB + c4 * 16;
            size_t ga = (size_t)(m0 + row) * 1024 + kb + c4 * 8;
            size_t gb = (size_t)(n0 + row) * 1024 + kb + c4 * 8;
            CP_ASYNC(base + 0 * ARR + off, Ah + ga);
            CP_ASYNC(base + 1 * ARR + off, Al + ga);
            CP_ASYNC(base + 2 * ARR + off, Bh + gb);
            CP_ASYNC(base + 3 * ARR + off, Bl + gb);
        }
        CP_COMMIT();
    };

    float acc[4][4][4];
#pragma unroll
    for (int i = 0; i < 4; i++)
#pragma unroll
        for (int j = 0; j < 4; j++)
#pragma unroll
            for (int e = 0; e < 4; e++) acc[i][j][e] = 0.f;

    fill(0, 0);
    for (int t = 0; t < 32; t++) {
        if (t + 1 < 32) { fill((t + 1) * 32, (t + 1) & 1); CP_WAIT(1); }
        else            { CP_WAIT(0); }
        __syncthreads();

        const uint32_t bb = sb + (t & 1) * BUF;
#pragma unroll
        for (int s = 0; s < 2; s++) {
            uint32_t ah[4][4], al[4][4];
            const int arow = wm + (lane & 15);
            const int acol = s * 16 + (lane >> 4) * 8;
#pragma unroll
            for (int i = 0; i < 4; i++) {
                uint32_t off = (uint32_t)(arow + i * 16) * GPB + acol * 2;
                ldsm4(ah[i][0], ah[i][1], ah[i][2], ah[i][3], bb + 0 * ARR + off);
                ldsm4(al[i][0], al[i][1], al[i][2], al[i][3], bb + 1 * ARR + off);
            }
            const int g = lane >> 3;
            const int brow = wn + (g >> 1) * 8 + (lane & 7);
            const int bcol = s * 16 + (g & 1) * 8;
#pragma unroll
            for (int p = 0; p < 2; p++) {
                uint32_t bh[4], bl[4];
                uint32_t off = (uint32_t)(brow + p * 16) * GPB + bcol * 2;
                ldsm4(bh[0], bh[1], bh[2], bh[3], bb + 2 * ARR + off);
                ldsm4(bl[0], bl[1], bl[2], bl[3], bb + 3 * ARR + off);
#pragma unroll
                for (int i = 0; i < 4; i++) mmabf(acc[i][2 * p],     ah[i], &bh[0]);
#pragma unroll
                for (int i = 0; i < 4; i++) mmabf(acc[i][2 * p + 1], ah[i], &bh[2]);
#pragma unroll
                for (int i = 0; i < 4; i++) mmabf(acc[i][2 * p],     ah[i], &bl[0]);
#pragma unroll
                for (int i = 0; i < 4; i++) mmabf(acc[i][2 * p + 1], ah[i], &bl[2]);
#pragma unroll
                for (int i = 0; i < 4; i++) mmabf(acc[i][2 * p],     al[i], &bh[0]);
#pragma unroll
                for (int i = 0; i < 4; i++) mmabf(acc[i][2 * p + 1], al[i], &bh[2]);
            }
        }
        __syncthreads();
    }

    const int r0 = m0 + wm + (lane >> 2);
    const int cb = n0 + wn + (lane & 3) * 2;
#pragma unroll
    for (int i = 0; i < 4; i++) {
#pragma unroll
        for (int half = 0; half < 2; half++) {
            int r = r0 + i * 16 + half * 8;
#pragma unroll
            for (int j = 0; j < 4; j++) {
                int c = cb + j * 8;
                float e0 = half ? acc[i][j][2] : acc[i][j][0];
                float e1 = half ? acc[i][j][3] : acc[i][j][1];
                if (MODE == 1) {
                    int which = c >> 10, cc = c & 1023;
                    int h = cc >> 6, dk = cc & 63;
                    int b = r >> 11, sdx = r & 2047;
                    size_t idx = (size_t)which * QSZ +
                                 ((((size_t)b * NHEAD + h) * SEQC + sdx) << 6) + dk;
                    uint32_t h32, l32;
                    split2(e0, e1, h32, l32);
                    Oh[idx >> 1] = h32;
                    Ol[idx >> 1] = l32;
                } else {
                    *(float2*)&C[(size_t)r * 1024 + c] = make_float2(e0, e1);
                }
            }
        }
    }
}

// ------------------ flash attention, bf16x3 mma, causal ----------------------
// 256-row Q tile, 512 threads (16 warps = 4/SMSP for softmax/mma overlap).
// Q smem resident all kernel (hi 0..36863, lo 36864..73727); Q frags re-ldsm'd
// per tile (saves 32 persistent regs -> no spills at the 128-reg cap).
#define AP 144
#define KVARR (64 * AP)          // 9216
#define STG (4 * KVARR)          // 36864 per KV stage
#define QHALF (256 * AP)         // 36864
#define QREG (2 * QHALF)         // 73728

__global__ __launch_bounds__(512, 1)
void attn_mma(const __nv_bfloat16* __restrict__ QKVh,
              const __nv_bfloat16* __restrict__ QKVl,
              uint32_t* __restrict__ AOh,
              uint32_t* __restrict__ AOl) {
    extern __shared__ char smc[];
    const uint32_t sb = su32(smc);
    const int tid = threadIdx.x, lane = tid & 31, w = tid >> 5;   // w: 0..15
    const int qt = blockIdx.x, bh = blockIdx.y;
    const int q0 = qt * 256;
    const int b = bh >> 4, h = bh & 15;

    const size_t bhoff = (size_t)bh * SEQC * 64;
    const __nv_bfloat16 *Qh = QKVh + bhoff,           *Ql = QKVl + bhoff;
    const __nv_bfloat16 *Kh = QKVh + QSZ + bhoff,     *Kl = QKVl + QSZ + bhoff;
    const __nv_bfloat16 *Vh = QKVh + 2 * QSZ + bhoff, *Vl = QKVl + 2 * QSZ + bhoff;

    auto fillkv = [&](int t, int buf) {
        uint32_t base = sb + QREG + buf * STG;
        int row = tid >> 3, c8 = tid & 7;          // 512 threads = 64x8 chunks
        uint32_t off = (uint32_t)row * AP + c8 * 16;
        size_t go = (size_t)(t * 64 + row) * 64 + c8 * 8;
        CP_ASYNC(base + 0 * KVARR + off, Kh + go);
        CP_ASYNC(base + 1 * KVARR + off, Kl + go);
        CP_ASYNC(base + 2 * KVARR + off, Vh + go);
        CP_ASYNC(base + 3 * KVARR + off, Vl + go);
        CP_COMMIT();
    };

    fillkv(0, 0);
    // Q tile fill: 256 rows x 8 chunks = 2048, 4 per thread
#pragma unroll
    for (int i = 0; i < 4; i++) {
        int idx = tid + i * 512;
        int row = idx >> 3, c8 = idx & 7;
        uint32_t off = (uint32_t)row * AP + c8 * 16;
        size_t go = (size_t)(q0 + row) * 64 + c8 * 8;
        *(uint4*)(smc + off) = *(const uint4*)(Qh + go);
        *(uint4*)(smc + QHALF + off) = *(const uint4*)(Ql + go);
    }
    __syncthreads();

    float o[8][4];
#pragma unroll
    for (int j = 0; j < 8; j++)
#pragma unroll
        for (int e = 0; e < 4; e++) o[j][e] = 0.f;
    float m_lo = -1e30f, m_hi = -1e30f, l_lo = 0.f, l_hi = 0.f;

    const int rlo = q0 + w * 16 + (lane >> 2);
    const int rhi = rlo + 8;
    const int g = lane >> 3;
    const int arow = w * 16 + (lane & 15);
    const int tmax = 4 * qt + 3;

    for (int t = 0; t <= tmax; t++) {
        if (t + 1 <= tmax) { fillkv(t + 1, (t + 1) & 1); CP_WAIT(1); }
        else               { CP_WAIT(0); }
        __syncthreads();

        const uint32_t bbase = sb + QREG + (uint32_t)(t & 1) * STG;
        const uint32_t KHo = bbase, KLo = bbase + KVARR,
                       VHo = bbase + 2 * KVARR, VLo = bbase + 3 * KVARR;

        float s_[8][4];
#pragma unroll
        for (int j = 0; j < 8; j++)
#pragma unroll
            for (int e = 0; e < 4; e++) s_[j][e] = 0.f;

        // S = Q K^T — Q frags re-ldsm'd per s; K frags hoisted; pass-major
#pragma unroll
        for (int s = 0; s < 4; s++) {
            uint32_t qhs[4], qls[4];
            {
                uint32_t qoff = (uint32_t)arow * AP + (s * 16 + (lane >> 4) * 8) * 2;
                ldsm4(qhs[0], qhs[1], qhs[2], qhs[3], sb + qoff);
                ldsm4(qls[0], qls[1], qls[2], qls[3], sb + QHALF + qoff);
            }
            const int brow = (g >> 1) * 8 + (lane & 7);
            const int bcol = s * 16 + (g & 1) * 8;
            uint32_t kh[4][4], kl[4][4];
#pragma unroll
            for (int p = 0; p < 4; p++) {
                uint32_t off = (uint32_t)(brow + p * 16) * AP + bcol * 2;
                ldsm4(kh[p][0], kh[p][1], kh[p][2], kh[p][3], KHo + off);
                ldsm4(kl[p][0], kl[p][1], kl[p][2], kl[p][3], KLo + off);
            }
#pragma unroll
            for (int p = 0; p < 4; p++) {
                mmabf(s_[2 * p],     qhs, &kh[p][0]);
                mmabf(s_[2 * p + 1], qhs, &kh[p][2]);
            }
#pragma unroll
            for (int p = 0; p < 4; p++) {
                mmabf(s_[2 * p],     qhs, &kl[p][0]);
                mmabf(s_[2 * p + 1], qhs, &kl[p][2]);
            }
#pragma unroll
            for (int p = 0; p < 4; p++) {
                mmabf(s_[2 * p],     qls, &kh[p][0]);
                mmabf(s_[2 * p + 1], qls, &kh[p][2]);
            }
        }

        const bool msk = (t >= 4 * qt);
#pragma unroll
        for (int j = 0; j < 8; j++) {
            int c = t * 64 + j * 8 + (lane & 3) * 2;
#pragma unroll
            for (int e = 0; e < 4; e++) s_[j][e] *= 0.125f;
            if (msk) {
                if (c > rlo)     s_[j][0] = -1e30f;
                if (c + 1 > rlo) s_[j][1] = -1e30f;
                if (c > rhi)     s_[j][2] = -1e30f;
                if (c + 1 > rhi) s_[j][3] = -1e30f;
            }
        }

        float rm_lo = -1e30f, rm_hi = -1e30f;
#pragma unroll
        for (int j = 0; j < 8; j++) {
            rm_lo = fmaxf(rm_lo, fmaxf(s_[j][0], s_[j][1]));
            rm_hi = fmaxf(rm_hi, fmaxf(s_[j][2], s_[j][3]));
        }
        rm_lo = fmaxf(rm_lo, __shfl_xor_sync(0xffffffffu, rm_lo, 1));
        rm_lo = fmaxf(rm_lo, __shfl_xor_sync(0xffffffffu, rm_lo, 2));
        rm_hi = fmaxf(rm_hi, __shfl_xor_sync(0xffffffffu, rm_hi, 1));
        rm_hi = fmaxf(rm_hi, __shfl_xor_sync(0xffffffffu, rm_hi, 2));
        float mn_lo = fmaxf(m_lo, rm_lo), mn_hi = fmaxf(m_hi, rm_hi);
        float cor_lo = __expf(m_lo - mn_lo), cor_hi = __expf(m_hi - mn_hi);
        m_lo = mn_lo; m_hi = mn_hi;
        float sum_lo = 0.f, sum_hi = 0.f;
#pragma unroll
        for (int j = 0; j < 8; j++) {
            s_[j][0] = __expf(s_[j][0] - mn_lo); sum_lo += s_[j][0];
            s_[j][1] = __expf(s_[j][1] - mn_lo); sum_lo += s_[j][1];
            s_[j][2] = __expf(s_[j][2] - mn_hi); sum_hi += s_[j][2];
            s_[j][3] = __expf(s_[j][3] - mn_hi); sum_hi += s_[j][3];
        }
        sum_lo += __shfl_xor_sync(0xffffffffu, sum_lo, 1);
        sum_lo += __shfl_xor_sync(0xffffffffu, sum_lo, 2);
        sum_hi += __shfl_xor_sync(0xffffffffu, sum_hi, 1);
        sum_hi += __shfl_xor_sync(0xffffffffu, sum_hi, 2);
        l_lo = l_lo * cor_lo + sum_lo;
        l_hi = l_hi * cor_hi + sum_hi;
#pragma unroll
        for (int j = 0; j < 8; j++) {
            o[j][0] *= cor_lo; o[j][1] *= cor_lo;
            o[j][2] *= cor_hi; o[j][3] *= cor_hi;
        }

        // O += P V — V frags hoisted per s; pass-major
#pragma unroll
        for (int s = 0; s < 4; s++) {
            uint32_t ph[4], pl[4];
            split2(s_[2 * s][0],     s_[2 * s][1],     ph[0], pl[0]);
            split2(s_[2 * s][2],     s_[2 * s][3],     ph[1], pl[1]);
            split2(s_[2 * s + 1][0], s_[2 * s + 1][1], ph[2], pl[2]);
            split2(s_[2 * s + 1][2], s_[2 * s + 1][3], ph[3], pl[3]);
            const int kvr = s * 16 + (g & 1) * 8 + (lane & 7);
            uint32_t vh[4][4], vl[4][4];
#pragma unroll
            for (int p = 0; p < 4; p++) {
                uint32_t off = (uint32_t)kvr * AP + ((g >> 1) * 8 + p * 16) * 2;
                ldsm4t(vh[p][0], vh[p][1], vh[p][2], vh[p][3], VHo + off);
                ldsm4t(vl[p][0], vl[p][1], vl[p][2], vl[p][3], VLo + off);
            }
#pragma unroll
            for (int p = 0; p < 4; p++) {
                mmabf(o[2 * p],     ph, &vh[p][0]);
                mmabf(o[2 * p + 1], ph, &vh[p][2]);
            }
#pragma unroll
            for (int p = 0; p < 4; p++) {
                mmabf(o[2 * p],     ph, &vl[p][0]);
                mmabf(o[2 * p + 1], ph, &vl[p][2]);
            }
#pragma unroll
            for (int p = 0; p < 4; p++) {
                mmabf(o[2 * p],     pl, &vh[p][0]);
                mmabf(o[2 * p + 1], pl, &vh[p][2]);
            }
        }
        __syncthreads();   // buffer (t&1) free for refill at iter t+1
    }

    const float il_lo = 1.f / l_lo, il_hi = 1.f / l_hi;
    const int colb = h * 64 + (lane & 3) * 2;
#pragma unroll
    for (int j = 0; j < 8; j++) {
        int col = colb + j * 8;
        size_t ilo = ((size_t)(b * SEQC + rlo) * DMOD + col);
        size_t ihi = ((size_t)(b * SEQC + rhi) * DMOD + col);
        uint32_t h32, l32;
        split2(o[j][0] * il_lo, o[j][1] * il_lo, h32, l32);
        AOh[ilo >> 1] = h32; AOl[ilo >> 1] = l32;
        split2(o[j][2] * il_hi, o[j][3] * il_hi, h32, l32);
        AOh[ihi >> 1] = h32; AOl[ihi >> 1] = l32;
    }
}

// ------------------------------ launch --------------------------------------
extern "C" void kernel_launch(void* const* d_in, const int* in_sizes, int n_in,
                              void* d_out, int out_size) {
    const float* x = (const float*)d_in[0];
    const float* W[4] = {(const float*)d_in[1], (const float*)d_in[2],
                         (const float*)d_in[3], (const float*)d_in[4]};
    float* out = (float*)d_out;

    __nv_bfloat16 *xh, *xl, *wh, *wl, *qkvh, *qkvl, *aoh, *aol;
    cudaGetSymbolAddress((void**)&xh, g_xh);
    cudaGetSymbolAddress((void**)&xl, g_xl);
    cudaGetSymbolAddress((void**)&wh, g_wh);
    cudaGetSymbolAddress((void**)&wl, g_wl);
    cudaGetSymbolAddress((void**)&qkvh, g_qkvh);
    cudaGetSymbolAddress((void**)&qkvl, g_qkvl);
    cudaGetSymbolAddress((void**)&aoh, g_aoh);
    cudaGetSymbolAddress((void**)&aol, g_aol);

    const int NW = DMOD * DMOD;
    const int n4x = MTOT * DMOD / 4, n4w = NW / 4;

    split_k<<<(n4x + 255) / 256, 256>>>((const float4*)x, (uint2*)xh, (uint2*)xl, n4x);
    for (int i = 0; i < 4; i++)
        split_k<<<(n4w + 255) / 256, 256>>>((const float4*)W[i],
                                            (uint2*)(wh + (size_t)i * NW),
                                            (uint2*)(wl + (size_t)i * NW), n4w);

    const int gshm = 2 * BUF;   // 81920
    cudaFuncSetAttribute(gemm_bf<1>, cudaFuncAttributeMaxDynamicSharedMemorySize, gshm);
    cudaFuncSetAttribute(gemm_bf<0>, cudaFuncAttributeMaxDynamicSharedMemorySize, gshm);

    // fused QKV projection: N = 3072
    gemm_bf<1><<<dim3(24, 64), 256, gshm>>>(xh, xl, wh, wl, nullptr,
                                            (uint32_t*)qkvh, (uint32_t*)qkvl);

    const int ashm = QREG + 2 * STG;   // 147456
    cudaFuncSetAttribute(attn_mma, cudaFuncAttributeMaxDynamicSharedMemorySize, ashm);
    attn_mma<<<dim3(SEQC / 256, BATCHC * NHEAD), 512, ashm>>>(qkvh, qkvl,
                                                              (uint32_t*)aoh,
                                                              (uint32_t*)aol);

    gemm_bf<0><<<dim3(8, 64), 256, gshm>>>(aoh, aol, wh + (size_t)3 * NW,
                                           wl + (size_t)3 * NW, out, nullptr, nullptr);
}

// round 11
// speedup vs baseline: 1.0376x; 1.0376x over previous
#include <cuda_runtime.h>
#include <cuda_bf16.h>
#include <cstdint>

#define SEQC 2048
#define BATCHC 4
#define NHEAD 16
#define DMOD 1024
#define MTOT (BATCHC * SEQC)     // 8192
#define QSZ (MTOT * DMOD)        // 8388608 elems per Q/K/V tensor (B*H*S*64)

__device__ __nv_bfloat16 g_xh[MTOT * DMOD], g_xl[MTOT * DMOD];
__device__ __nv_bfloat16 g_wh[4 * DMOD * DMOD], g_wl[4 * DMOD * DMOD];
__device__ __nv_bfloat16 g_qkvh[3 * QSZ], g_qkvl[3 * QSZ];
__device__ __nv_bfloat16 g_aoh[MTOT * DMOD], g_aol[MTOT * DMOD];

// ------------------------------ helpers -------------------------------------
__device__ __forceinline__ uint32_t su32(const void* p) {
    uint32_t a;
    asm("{ .reg .u64 t; cvta.to.shared.u64 t, %1; cvt.u32.u64 %0, t; }" : "=r"(a) : "l"(p));
    return a;
}
__device__ __forceinline__ uint32_t pk2(float e0, float e1) {
    uint32_t d;
    asm("cvt.rn.bf16x2.f32 %0, %1, %2;" : "=r"(d) : "f"(e1), "f"(e0));
    return d;
}
__device__ __forceinline__ void split2(float a, float b, uint32_t& h, uint32_t& l) {
    float ha = __bfloat162float(__float2bfloat16(a));
    float hb = __bfloat162float(__float2bfloat16(b));
    h = pk2(ha, hb);
    l = pk2(a - ha, b - hb);
}
__device__ __forceinline__ void ldsm4(uint32_t& r0, uint32_t& r1, uint32_t& r2,
                                      uint32_t& r3, uint32_t a) {
    asm volatile("ldmatrix.sync.aligned.m8n8.x4.shared.b16 {%0,%1,%2,%3}, [%4];"
                 : "=r"(r0), "=r"(r1), "=r"(r2), "=r"(r3) : "r"(a));
}
__device__ __forceinline__ void ldsm4t(uint32_t& r0, uint32_t& r1, uint32_t& r2,
                                       uint32_t& r3, uint32_t a) {
    asm volatile("ldmatrix.sync.aligned.m8n8.x4.trans.shared.b16 {%0,%1,%2,%3}, [%4];"
                 : "=r"(r0), "=r"(r1), "=r"(r2), "=r"(r3) : "r"(a));
}
__device__ __forceinline__ void mmabf(float* c, const uint32_t* a, const uint32_t* b) {
    asm volatile(
        "mma.sync.aligned.m16n8k16.row.col.f32.bf16.bf16.f32 "
        "{%0,%1,%2,%3},{%4,%5,%6,%7},{%8,%9},{%0,%1,%2,%3};"
        : "+f"(c[0]), "+f"(c[1]), "+f"(c[2]), "+f"(c[3])
        : "r"(a[0]), "r"(a[1]), "r"(a[2]), "r"(a[3]), "r"(b[0]), "r"(b[1]));
}
#define CP_ASYNC(dst, src) \
    asm volatile("cp.async.ca.shared.global [%0], [%1], 16;" :: "r"(dst), "l"(src) : "memory")
#define CP_COMMIT() asm volatile("cp.async.commit_group;" ::: "memory")
#define CP_WAIT(n)  asm volatile("cp.async.wait_group %0;" :: "n"(n) : "memory")

// --------------- fp32 -> bf16 hi/lo split, ALL tensors in one launch ---------
#define N4X (MTOT * DMOD / 4)    // 2097152 float4 in x
#define N4W (DMOD * DMOD / 4)    // 262144 float4 per weight

__global__ void split_all(const float4* __restrict__ x,
                          const float4* __restrict__ w0, const float4* __restrict__ w1,
                          const float4* __restrict__ w2, const float4* __restrict__ w3,
                          uint2* __restrict__ xh, uint2* __restrict__ xl,
                          uint2* __restrict__ wh, uint2* __restrict__ wl) {
    int i = blockIdx.x * blockDim.x + threadIdx.x;
    const float4* src;
    uint2 *hi, *lo;
    int off;
    if (i < N4X) {
        src = x; hi = xh; lo = xl; off = i;
    } else {
        int j = i - N4X;
        int wsel = j >> 18;              // j / N4W  (N4W = 2^18)
        off = j & (N4W - 1);
        src = (wsel == 0) ? w0 : (wsel == 1) ? w1 : (wsel == 2) ? w2 : w3;
        hi = wh + (size_t)wsel * N4W;
        lo = wl + (size_t)wsel * N4W;
    }
    float4 v = src[off];
    uint32_t h0, l0, h1, l1;
    split2(v.x, v.y, h0, l0);
    split2(v.z, v.w, h1, l1);
    hi[off] = make_uint2(h0, h1);
    lo[off] = make_uint2(l0, l1);
}

// ---------- GEMM: C[M,N] = A[M,1024] B[N,1024]^T, bf16x3 (R9-verbatim) -------
#define GPB 80
#define ARR (128 * GPB)
#define BUF (4 * ARR)

template <int MODE>                  // 1: split-QKV bf16 out, 0: fp32 out
__global__ __launch_bounds__(256, 2) void gemm_bf(const __nv_bfloat16* __restrict__ Ah,
                                                  const __nv_bfloat16* __restrict__ Al,
                                                  const __nv_bfloat16* __restrict__ Bh,
                                                  const __nv_bfloat16* __restrict__ Bl,
                                                  float* __restrict__ C,
                                                  uint32_t* __restrict__ Oh,
                                                  uint32_t* __restrict__ Ol) {
    extern __shared__ char sm[];
    const uint32_t sb = su32(sm);
    const int tid = threadIdx.x, lane = tid & 31, wid = tid >> 5;
    const int m0 = blockIdx.y * 128, n0 = blockIdx.x * 128;
    const int wm = (wid >> 2) * 64, wn = (wid & 3) * 32;

    auto fill = [&](int kb, int buf) {
        uint32_t base = sb + buf * BUF;
#pragma unroll
        for (int i = 0; i < 2; i++) {
            int idx = tid + i * 256;
            int row = idx >> 2, c4 = idx & 3;
            uint32_t off = (uint32_t)row * GPB + c4 * 16;
            size_t ga = (size_t)(m0 + row) * 1024 + kb + c4 * 8;
            size_t gb = (size_t)(n0 + row) * 1024 + kb + c4 * 8;
            CP_ASYNC(base + 0 * ARR + off, Ah + ga);
            CP_ASYNC(base + 1 * ARR + off, Al + ga);
            CP_ASYNC(base + 2 * ARR + off, Bh + gb);
            CP_ASYNC(base + 3 * ARR + off, Bl + gb);
        }
        CP_COMMIT();
    };

    float acc[4][4][4];
#pragma unroll
    for (int i = 0; i < 4; i++)
#pragma unroll
        for (int j = 0; j < 4; j++)
#pragma unroll
            for (int e = 0; e < 4; e++) acc[i][j][e] = 0.f;

    fill(0, 0);
    for (int t = 0; t < 32; t++) {
        if (t + 1 < 32) { fill((t + 1) * 32, (t + 1) & 1); CP_WAIT(1); }
        else            { CP_WAIT(0); }
        __syncthreads();

        const uint32_t bb = sb + (t & 1) * BUF;
#pragma unroll
        for (int s = 0; s < 2; s++) {
            uint32_t ah[4][4], al[4][4];
            const int arow = wm + (lane & 15);
            const int acol = s * 16 + (lane >> 4) * 8;
#pragma unroll
            for (int i = 0; i < 4; i++) {
                uint32_t off = (uint32_t)(arow + i * 16) * GPB + acol * 2;
                ldsm4(ah[i][0], ah[i][1], ah[i][2], ah[i][3], bb + 0 * ARR + off);
                ldsm4(al[i][0], al[i][1], al[i][2], al[i][3], bb + 1 * ARR + off);
            }
            const int g = lane >> 3;
            const int brow = wn + (g >> 1) * 8 + (lane & 7);
            const int bcol = s * 16 + (g & 1) * 8;
#pragma unroll
            for (int p = 0; p < 2; p++) {
                uint32_t bh[4], bl[4];
                uint32_t off = (uint32_t)(brow + p * 16) * GPB + bcol * 2;
                ldsm4(bh[0], bh[1], bh[2], bh[3], bb + 2 * ARR + off);
                ldsm4(bl[0], bl[1], bl[2], bl[3], bb + 3 * ARR + off);
#pragma unroll
                for (int i = 0; i < 4; i++) mmabf(acc[i][2 * p],     ah[i], &bh[0]);
#pragma unroll
                for (int i = 0; i < 4; i++) mmabf(acc[i][2 * p + 1], ah[i], &bh[2]);
#pragma unroll
                for (int i = 0; i < 4; i++) mmabf(acc[i][2 * p],     ah[i], &bl[0]);
#pragma unroll
                for (int i = 0; i < 4; i++) mmabf(acc[i][2 * p + 1], ah[i], &bl[2]);
#pragma unroll
                for (int i = 0; i < 4; i++) mmabf(acc[i][2 * p],     al[i], &bh[0]);
#pragma unroll
                for (int i = 0; i < 4; i++) mmabf(acc[i][2 * p + 1], al[i], &bh[2]);
            }
        }
        __syncthreads();
    }

    const int r0 = m0 + wm + (lane >> 2);
    const int cb = n0 + wn + (lane & 3) * 2;
#pragma unroll
    for (int i = 0; i < 4; i++) {
#pragma unroll
        for (int half = 0; half < 2; half++) {
            int r = r0 + i * 16 + half * 8;
#pragma unroll
            for (int j = 0; j < 4; j++) {
                int c = cb + j * 8;
                float e0 = half ? acc[i][j][2] : acc[i][j][0];
                float e1 = half ? acc[i][j][3] : acc[i][j][1];
                if (MODE == 1) {
                    int which = c >> 10, cc = c & 1023;
                    int h = cc >> 6, dk = cc & 63;
                    int b = r >> 11, sdx = r & 2047;
                    size_t idx = (size_t)which * QSZ +
                                 ((((size_t)b * NHEAD + h) * SEQC + sdx) << 6) + dk;
                    uint32_t h32, l32;
                    split2(e0, e1, h32, l32);
                    Oh[idx >> 1] = h32;
                    Ol[idx >> 1] = l32;
                } else {
                    *(float2*)&C[(size_t)r * 1024 + c] = make_float2(e0, e1);
                }
            }
        }
    }
}

// ------------------ flash attention, bf16x3 mma, causal (R9-verbatim) --------
#define AP 144
#define KVARR (64 * AP)          // 9216
#define STG (4 * KVARR)          // 36864 per KV stage
#define QREG (2 * 128 * AP)      // 36864 Q hi+lo

__global__ void attn_mma(const __nv_bfloat16* __restrict__ QKVh,
                         const __nv_bfloat16* __restrict__ QKVl,
                         uint32_t* __restrict__ AOh,
                         uint32_t* __restrict__ AOl) {
    extern __shared__ char smc[];
    const uint32_t sb = su32(smc);
    const int tid = threadIdx.x, lane = tid & 31, w = tid >> 5;
    const int qt = blockIdx.x, bh = blockIdx.y;
    const int q0 = qt * 128;
    const int b = bh >> 4, h = bh & 15;

    const size_t bhoff = (size_t)bh * SEQC * 64;
    const __nv_bfloat16 *Qh = QKVh + bhoff,           *Ql = QKVl + bhoff;
    const __nv_bfloat16 *Kh = QKVh + QSZ + bhoff,     *Kl = QKVl + QSZ + bhoff;
    const __nv_bfloat16 *Vh = QKVh + 2 * QSZ + bhoff, *Vl = QKVl + 2 * QSZ + bhoff;

    auto fillkv = [&](int t, int buf) {
        uint32_t base = sb + QREG + buf * STG;
#pragma unroll
        for (int i = 0; i < 2; i++) {
            int idx = tid + i * 256;           // 0..511
            int row = idx >> 3, c8 = idx & 7;
            uint32_t off = (uint32_t)row * AP + c8 * 16;
            size_t go = (size_t)(t * 64 + row) * 64 + c8 * 8;
            CP_ASYNC(base + 0 * KVARR + off, Kh + go);
            CP_ASYNC(base + 1 * KVARR + off, Kl + go);
            CP_ASYNC(base + 2 * KVARR + off, Vh + go);
            CP_ASYNC(base + 3 * KVARR + off, Vl + go);
        }
        CP_COMMIT();
    };

    fillkv(0, 0);
#pragma unroll
    for (int i = 0; i < 4; i++) {
        int idx = tid + i * 256;
        int row = idx >> 3, c8 = idx & 7;
        uint32_t off = (uint32_t)row * AP + c8 * 16;
        size_t go = (size_t)(q0 + row) * 64 + c8 * 8;
        *(uint4*)(smc + off) = *(const uint4*)(Qh + go);
        *(uint4*)(smc + 128 * AP + off) = *(const uint4*)(Ql + go);
    }
    __syncthreads();

    uint32_t qh[4][4], ql[4][4];
    {
        const int arow = w * 16 + (lane & 15);
#pragma unroll
        for (int s = 0; s < 4; s++) {
            uint32_t off = (uint32_t)arow * AP + (s * 16 + (lane >> 4) * 8) * 2;
            ldsm4(qh[s][0], qh[s][1], qh[s][2], qh[s][3], sb + off);
            ldsm4(ql[s][0], ql[s][1], ql[s][2], ql[s][3], sb + 128 * AP + off);
        }
    }

    float o[8][4];
#pragma unroll
    for (int j = 0; j < 8; j++)
#pragma unroll
        for (int e = 0; e < 4; e++) o[j][e] = 0.f;
    float m_lo = -1e30f, m_hi = -1e30f, l_lo = 0.f, l_hi = 0.f;

    const int rlo = q0 + w * 16 + (lane >> 2);
    const int rhi = rlo + 8;
    const int g = lane >> 3;
    const int tmax = 2 * qt + 1;

    for (int t = 0; t <= tmax; t++) {
        if (t + 1 <= tmax) { fillkv(t + 1, (t + 1) & 1); CP_WAIT(1); }
        else               { CP_WAIT(0); }
        __syncthreads();

        const uint32_t bbase = sb + QREG + (uint32_t)(t & 1) * STG;
        const uint32_t KHo = bbase, KLo = bbase + KVARR,
                       VHo = bbase + 2 * KVARR, VLo = bbase + 3 * KVARR;

        float s_[8][4];
#pragma unroll
        for (int j = 0; j < 8; j++)
#pragma unroll
            for (int e = 0; e < 4; e++) s_[j][e] = 0.f;

#pragma unroll
        for (int s = 0; s < 4; s++) {
            const int brow = (g >> 1) * 8 + (lane & 7);
            const int bcol = s * 16 + (g & 1) * 8;
            uint32_t kh[4][4], kl[4][4];
#pragma unroll
            for (int p = 0; p < 4; p++) {
                uint32_t off = (uint32_t)(brow + p * 16) * AP + bcol * 2;
                ldsm4(kh[p][0], kh[p][1], kh[p][2], kh[p][3], KHo + off);
                ldsm4(kl[p][0], kl[p][1], kl[p][2], kl[p][3], KLo + off);
            }
#pragma unroll
            for (int p = 0; p < 4; p++) {
                mmabf(s_[2 * p],     qh[s], &kh[p][0]);
                mmabf(s_[2 * p + 1], qh[s], &kh[p][2]);
            }
#pragma unroll
            for (int p = 0; p < 4; p++) {
                mmabf(s_[2 * p],     qh[s], &kl[p][0]);
                mmabf(s_[2 * p + 1], qh[s], &kl[p][2]);
            }
#pragma unroll
            for (int p = 0; p < 4; p++) {
                mmabf(s_[2 * p],     ql[s], &kh[p][0]);
                mmabf(s_[2 * p + 1], ql[s], &kh[p][2]);
            }
        }

        const bool msk = (t >= 2 * qt);
#pragma unroll
        for (int j = 0; j < 8; j++) {
            int c = t * 64 + j * 8 + (lane & 3) * 2;
#pragma unroll
            for (int e = 0; e < 4; e++) s_[j][e] *= 0.125f;
            if (msk) {
                if (c > rlo)     s_[j][0] = -1e30f;
                if (c + 1 > rlo) s_[j][1] = -1e30f;
                if (c > rhi)     s_[j][2] = -1e30f;
                if (c + 1 > rhi) s_[j][3] = -1e30f;
            }
        }

        float rm_lo = -1e30f, rm_hi = -1e30f;
#pragma unroll
        for (int j = 0; j < 8; j++) {
            rm_lo = fmaxf(rm_lo, fmaxf(s_[j][0], s_[j][1]));
            rm_hi = fmaxf(rm_hi, fmaxf(s_[j][2], s_[j][3]));
        }
        rm_lo = fmaxf(rm_lo, __shfl_xor_sync(0xffffffffu, rm_lo, 1));
        rm_lo = fmaxf(rm_lo, __shfl_xor_sync(0xffffffffu, rm_lo, 2));
        rm_hi = fmaxf(rm_hi, __shfl_xor_sync(0xffffffffu, rm_hi, 1));
        rm_hi = fmaxf(rm_hi, __shfl_xor_sync(0xffffffffu, rm_hi, 2));
        float mn_lo = fmaxf(m_lo, rm_lo), mn_hi = fmaxf(m_hi, rm_hi);
        float cor_lo = __expf(m_lo - mn_lo), cor_hi = __expf(m_hi - mn_hi);
        m_lo = mn_lo; m_hi = mn_hi;
        float sum_lo = 0.f, sum_hi = 0.f;
#pragma unroll
        for (int j = 0; j < 8; j++) {
            s_[j][0] = __expf(s_[j][0] - mn_lo); sum_lo += s_[j][0];
            s_[j][1] = __expf(s_[j][1] - mn_lo); sum_lo += s_[j][1];
            s_[j][2] = __expf(s_[j][2] - mn_hi); sum_hi += s_[j][2];
            s_[j][3] = __expf(s_[j][3] - mn_hi); sum_hi += s_[j][3];
        }
        sum_lo += __shfl_xor_sync(0xffffffffu, sum_lo, 1);
        sum_lo += __shfl_xor_sync(0xffffffffu, sum_lo, 2);
        sum_hi += __shfl_xor_sync(0xffffffffu, sum_hi, 1);
        sum_hi += __shfl_xor_sync(0xffffffffu, sum_hi, 2);
        l_lo = l_lo * cor_lo + sum_lo;
        l_hi = l_hi * cor_hi + sum_hi;
#pragma unroll
        for (int j = 0; j < 8; j++) {
            o[j][0] *= cor_lo; o[j][1] *= cor_lo;
            o[j][2] *= cor_hi; o[j][3] *= cor_hi;
        }

#pragma unroll
        for (int s = 0; s < 4; s++) {
            uint32_t ph[4], pl[4];
            split2(s_[2 * s][0],     s_[2 * s][1],     ph[0], pl[0]);
            split2(s_[2 * s][2],     s_[2 * s][3],     ph[1], pl[1]);
            split2(s_[2 * s + 1][0], s_[2 * s + 1][1], ph[2], pl[2]);
            split2(s_[2 * s + 1][2], s_[2 * s + 1][3], ph[3], pl[3]);
            const int kvr = s * 16 + (g & 1) * 8 + (lane & 7);
            uint32_t vh[4][4], vl[4][4];
#pragma unroll
            for (int p = 0; p < 4; p++) {
                uint32_t off = (uint32_t)kvr * AP + ((g >> 1) * 8 + p * 16) * 2;
                ldsm4t(vh[p][0], vh[p][1], vh[p][2], vh[p][3], VHo + off);
                ldsm4t(vl[p][0], vl[p][1], vl[p][2], vl[p][3], VLo + off);
            }
#pragma unroll
            for (int p = 0; p < 4; p++) {
                mmabf(o[2 * p],     ph, &vh[p][0]);
                mmabf(o[2 * p + 1], ph, &vh[p][2]);
            }
#pragma unroll
            for (int p = 0; p < 4; p++) {
                mmabf(o[2 * p],     ph, &vl[p][0]);
                mmabf(o[2 * p + 1], ph, &vl[p][2]);
            }
#pragma unroll
            for (int p = 0; p < 4; p++) {
                mmabf(o[2 * p],     pl, &vh[p][0]);
                mmabf(o[2 * p + 1], pl, &vh[p][2]);
            }
        }
        __syncthreads();   // buffer (t&1) free for refill at iter t+1
    }

    const float il_lo = 1.f / l_lo, il_hi = 1.f / l_hi;
    const int colb = h * 64 + (lane & 3) * 2;
#pragma unroll
    for (int j = 0; j < 8; j++) {
        int col = colb + j * 8;
        size_t ilo = ((size_t)(b * SEQC + rlo) * DMOD + col);
        size_t ihi = ((size_t)(b * SEQC + rhi) * DMOD + col);
        uint32_t h32, l32;
        split2(o[j][0] * il_lo, o[j][1] * il_lo, h32, l32);
        AOh[ilo >> 1] = h32; AOl[ilo >> 1] = l32;
        split2(o[j][2] * il_hi, o[j][3] * il_hi, h32, l32);
        AOh[ihi >> 1] = h32; AOl[ihi >> 1] = l32;
    }
}

// ------------------------------ launch --------------------------------------
extern "C" void kernel_launch(void* const* d_in, const int* in_sizes, int n_in,
                              void* d_out, int out_size) {
    const float* x = (const float*)d_in[0];
    float* out = (float*)d_out;

    __nv_bfloat16 *xh, *xl, *wh, *wl, *qkvh, *qkvl, *aoh, *aol;
    cudaGetSymbolAddress((void**)&xh, g_xh);
    cudaGetSymbolAddress((void**)&xl, g_xl);
    cudaGetSymbolAddress((void**)&wh, g_wh);
    cudaGetSymbolAddress((void**)&wl, g_wl);
    cudaGetSymbolAddress((void**)&qkvh, g_qkvh);
    cudaGetSymbolAddress((void**)&qkvl, g_qkvl);
    cudaGetSymbolAddress((void**)&aoh, g_aoh);
    cudaGetSymbolAddress((void**)&aol, g_aol);

    const int NW = DMOD * DMOD;

    // one launch splits x + all 4 weights (12288 blocks)
    split_all<<<(N4X + 4 * N4W + 255) / 256, 256>>>(
        (const float4*)x, (const float4*)d_in[1], (const float4*)d_in[2],
        (const float4*)d_in[3], (const float4*)d_in[4],
        (uint2*)xh, (uint2*)xl, (uint2*)wh, (uint2*)wl);

    const int gshm = 2 * BUF;   // 81920
    cudaFuncSetAttribute(gemm_bf<1>, cudaFuncAttributeMaxDynamicSharedMemorySize, gshm);
    cudaFuncSetAttribute(gemm_bf<0>, cudaFuncAttributeMaxDynamicSharedMemorySize, gshm);

    // fused QKV projection: N = 3072
    gemm_bf<1><<<dim3(24, 64), 256, gshm>>>(xh, xl, wh, wl, nullptr,
                                            (uint32_t*)qkvh, (uint32_t*)qkvl);

    const int ashm = QREG + 2 * STG;   // 110592
    cudaFuncSetAttribute(attn_mma, cudaFuncAttributeMaxDynamicSharedMemorySize, ashm);
    attn_mma<<<dim3(SEQC / 128, BATCHC * NHEAD), 256, ashm>>>(qkvh, qkvl,
                                                              (uint32_t*)aoh,
                                                              (uint32_t*)aol);

    gemm_bf<0><<<dim3(8, 64), 256, gshm>>>(aoh, aol, wh + (size_t)3 * NW,
                                           wl + (size_t)3 * NW, out, nullptr, nullptr);
}

// round 12
// speedup vs baseline: 1.3060x; 1.2587x over previous
#include <cuda_runtime.h>
#include <cuda_bf16.h>
#include <cuda_fp16.h>
#include <cstdint>

#define SEQC 2048
#define BATCHC 4
#define NHEAD 16
#define DMOD 1024
#define MTOT (BATCHC * SEQC)     // 8192
#define QSZ (MTOT * DMOD)        // 8388608 elems per Q/K/V tensor (B*H*S*64)

__device__ __nv_bfloat16 g_xh[MTOT * DMOD], g_xl[MTOT * DMOD];
__device__ __nv_bfloat16 g_wh[4 * DMOD * DMOD], g_wl[4 * DMOD * DMOD];
__device__ __half g_qkv[3 * QSZ];                     // fp16 Q/K/V
__device__ __nv_bfloat16 g_aoh[MTOT * DMOD], g_aol[MTOT * DMOD];

// ------------------------------ helpers -------------------------------------
__device__ __forceinline__ uint32_t su32(const void* p) {
    uint32_t a;
    asm("{ .reg .u64 t; cvta.to.shared.u64 t, %1; cvt.u32.u64 %0, t; }" : "=r"(a) : "l"(p));
    return a;
}
__device__ __forceinline__ uint32_t pk2(float e0, float e1) {       // bf16x2
    uint32_t d;
    asm("cvt.rn.bf16x2.f32 %0, %1, %2;" : "=r"(d) : "f"(e1), "f"(e0));
    return d;
}
__device__ __forceinline__ uint32_t pk2h(float e0, float e1) {      // f16x2
    uint32_t d;
    asm("cvt.rn.f16x2.f32 %0, %1, %2;" : "=r"(d) : "f"(e1), "f"(e0));
    return d;
}
__device__ __forceinline__ void split2(float a, float b, uint32_t& h, uint32_t& l) {
    float ha = __bfloat162float(__float2bfloat16(a));
    float hb = __bfloat162float(__float2bfloat16(b));
    h = pk2(ha, hb);
    l = pk2(a - ha, b - hb);
}
__device__ __forceinline__ void ldsm4(uint32_t& r0, uint32_t& r1, uint32_t& r2,
                                      uint32_t& r3, uint32_t a) {
    asm volatile("ldmatrix.sync.aligned.m8n8.x4.shared.b16 {%0,%1,%2,%3}, [%4];"
                 : "=r"(r0), "=r"(r1), "=r"(r2), "=r"(r3) : "r"(a));
}
__device__ __forceinline__ void ldsm4t(uint32_t& r0, uint32_t& r1, uint32_t& r2,
                                       uint32_t& r3, uint32_t a) {
    asm volatile("ldmatrix.sync.aligned.m8n8.x4.trans.shared.b16 {%0,%1,%2,%3}, [%4];"
                 : "=r"(r0), "=r"(r1), "=r"(r2), "=r"(r3) : "r"(a));
}
__device__ __forceinline__ void mmabf(float* c, const uint32_t* a, const uint32_t* b) {
    asm volatile(
        "mma.sync.aligned.m16n8k16.row.col.f32.bf16.bf16.f32 "
        "{%0,%1,%2,%3},{%4,%5,%6,%7},{%8,%9},{%0,%1,%2,%3};"
        : "+f"(c[0]), "+f"(c[1]), "+f"(c[2]), "+f"(c[3])
        : "r"(a[0]), "r"(a[1]), "r"(a[2]), "r"(a[3]), "r"(b[0]), "r"(b[1]));
}
__device__ __forceinline__ void mmah(float* c, const uint32_t* a, const uint32_t* b) {
    asm volatile(
        "mma.sync.aligned.m16n8k16.row.col.f32.f16.f16.f32 "
        "{%0,%1,%2,%3},{%4,%5,%6,%7},{%8,%9},{%0,%1,%2,%3};"
        : "+f"(c[0]), "+f"(c[1]), "+f"(c[2]), "+f"(c[3])
        : "r"(a[0]), "r"(a[1]), "r"(a[2]), "r"(a[3]), "r"(b[0]), "r"(b[1]));
}
#define CP_ASYNC(dst, src) \
    asm volatile("cp.async.ca.shared.global [%0], [%1], 16;" :: "r"(dst), "l"(src) : "memory")
#define CP_COMMIT() asm volatile("cp.async.commit_group;" ::: "memory")
#define CP_WAIT(n)  asm volatile("cp.async.wait_group %0;" :: "n"(n) : "memory")

// --------------- fp32 -> bf16 hi/lo split, ALL tensors in one launch ---------
#define N4X (MTOT * DMOD / 4)
#define N4W (DMOD * DMOD / 4)

__global__ void split_all(const float4* __restrict__ x,
                          const float4* __restrict__ w0, const float4* __restrict__ w1,
                          const float4* __restrict__ w2, const float4* __restrict__ w3,
                          uint2* __restrict__ xh, uint2* __restrict__ xl,
                          uint2* __restrict__ wh, uint2* __restrict__ wl) {
    int i = blockIdx.x * blockDim.x + threadIdx.x;
    const float4* src;
    uint2 *hi, *lo;
    int off;
    if (i < N4X) {
        src = x; hi = xh; lo = xl; off = i;
    } else {
        int j = i - N4X;
        int wsel = j >> 18;
        off = j & (N4W - 1);
        src = (wsel == 0) ? w0 : (wsel == 1) ? w1 : (wsel == 2) ? w2 : w3;
        hi = wh + (size_t)wsel * N4W;
        lo = wl + (size_t)wsel * N4W;
    }
    float4 v = src[off];
    uint32_t h0, l0, h1, l1;
    split2(v.x, v.y, h0, l0);
    split2(v.z, v.w, h1, l1);
    hi[off] = make_uint2(h0, h1);
    lo[off] = make_uint2(l0, l1);
}

// ---------- GEMM: C[M,N] = A[M,1024] B[N,1024]^T, bf16x3 ---------------------
#define GPB 80
#define ARR (128 * GPB)
#define BUF (4 * ARR)

template <int MODE>                  // 1: fp16 QKV out, 0: fp32 out
__global__ __launch_bounds__(256, 2) void gemm_bf(const __nv_bfloat16* __restrict__ Ah,
                                                  const __nv_bfloat16* __restrict__ Al,
                                                  const __nv_bfloat16* __restrict__ Bh,
                                                  const __nv_bfloat16* __restrict__ Bl,
                                                  float* __restrict__ C,
                                                  uint32_t* __restrict__ Oh) {
    extern __shared__ char sm[];
    const uint32_t sb = su32(sm);
    const int tid = threadIdx.x, lane = tid & 31, wid = tid >> 5;
    const int m0 = blockIdx.y * 128, n0 = blockIdx.x * 128;
    const int wm = (wid >> 2) * 64, wn = (wid & 3) * 32;

    auto fill = [&](int kb, int buf) {
        uint32_t base = sb + buf * BUF;
#pragma unroll
        for (int i = 0; i < 2; i++) {
            int idx = tid + i * 256;
            int row = idx >> 2, c4 = idx & 3;
            uint32_t off = (uint32_t)row * GPB + c4 * 16;
            size_t ga = (size_t)(m0 + row) * 1024 + kb + c4 * 8;
            size_t gb = (size_t)(n0 + row) * 1024 + kb + c4 * 8;
            CP_ASYNC(base + 0 * ARR + off, Ah + ga);
            CP_ASYNC(base + 1 * ARR + off, Al + ga);
            CP_ASYNC(base + 2 * ARR + off, Bh + gb);
            CP_ASYNC(base + 3 * ARR + off, Bl + gb);
        }
        CP_COMMIT();
    };

    float acc[4][4][4];
#pragma unroll
    for (int i = 0; i < 4; i++)
#pragma unroll
        for (int j = 0; j < 4; j++)
#pragma unroll
            for (int e = 0; e < 4; e++) acc[i][j][e] = 0.f;

    fill(0, 0);
    for (int t = 0; t < 32; t++) {
        if (t + 1 < 32) { fill((t + 1) * 32, (t + 1) & 1); CP_WAIT(1); }
        else            { CP_WAIT(0); }
        __syncthreads();

        const uint32_t bb = sb + (t & 1) * BUF;
#pragma unroll
        for (int s = 0; s < 2; s++) {
            uint32_t ah[4][4], al[4][4];
            const int arow = wm + (lane & 15);
            const int acol = s * 16 + (lane >> 4) * 8;
#pragma unroll
            for (int i = 0; i < 4; i++) {
                uint32_t off = (uint32_t)(arow + i * 16) * GPB + acol * 2;
                ldsm4(ah[i][0], ah[i][1], ah[i][2], ah[i][3], bb + 0 * ARR + off);
                ldsm4(al[i][0], al[i][1], al[i][2], al[i][3], bb + 1 * ARR + off);
            }
            const int g = lane >> 3;
            const int brow = wn + (g >> 1) * 8 + (lane & 7);
            const int bcol = s * 16 + (g & 1) * 8;
#pragma unroll
            for (int p = 0; p < 2; p++) {
                uint32_t bh[4], bl[4];
                uint32_t off = (uint32_t)(brow + p * 16) * GPB + bcol * 2;
                ldsm4(bh[0], bh[1], bh[2], bh[3], bb + 2 * ARR + off);
                ldsm4(bl[0], bl[1], bl[2], bl[3], bb + 3 * ARR + off);
#pragma unroll
                for (int i = 0; i < 4; i++) mmabf(acc[i][2 * p],     ah[i], &bh[0]);
#pragma unroll
                for (int i = 0; i < 4; i++) mmabf(acc[i][2 * p + 1], ah[i], &bh[2]);
#pragma unroll
                for (int i = 0; i < 4; i++) mmabf(acc[i][2 * p],     ah[i], &bl[0]);
#pragma unroll
                for (int i = 0; i < 4; i++) mmabf(acc[i][2 * p + 1], ah[i], &bl[2]);
#pragma unroll
                for (int i = 0; i < 4; i++) mmabf(acc[i][2 * p],     al[i], &bh[0]);
#pragma unroll
                for (int i = 0; i < 4; i++) mmabf(acc[i][2 * p + 1], al[i], &bh[2]);
            }
        }
        __syncthreads();
    }

    const int r0 = m0 + wm + (lane >> 2);
    const int cb = n0 + wn + (lane & 3) * 2;
#pragma unroll
    for (int i = 0; i < 4; i++) {
#pragma unroll
        for (int half = 0; half < 2; half++) {
            int r = r0 + i * 16 + half * 8;
#pragma unroll
            for (int j = 0; j < 4; j++) {
                int c = cb + j * 8;
                float e0 = half ? acc[i][j][2] : acc[i][j][0];
                float e1 = half ? acc[i][j][3] : acc[i][j][1];
                if (MODE == 1) {
                    int which = c >> 10, cc = c & 1023;
                    int h = cc >> 6, dk = cc & 63;
                    int b = r >> 11, sdx = r & 2047;
                    size_t idx = (size_t)which * QSZ +
                                 ((((size_t)b * NHEAD + h) * SEQC + sdx) << 6) + dk;
                    Oh[idx >> 1] = pk2h(e0, e1);
                } else {
                    *(float2*)&C[(size_t)r * 1024 + c] = make_float2(e0, e1);
                }
            }
        }
    }
}

// ------------------ flash attention, fp16 single-pass mma, causal ------------
#define AP 144
#define KVARR (64 * AP)          // 9216 per K or V array
#define STG (2 * KVARR)          // 18432 per KV stage
#define QREGA (128 * AP)         // 18432 fp16 Q tile

__global__ void attn_mma(const __half* __restrict__ QKV,
                         uint32_t* __restrict__ AOh,
                         uint32_t* __restrict__ AOl) {
    extern __shared__ char smc[];
    const uint32_t sb = su32(smc);
    const int tid = threadIdx.x, lane = tid & 31, w = tid >> 5;
    const int qt = blockIdx.x, bh = blockIdx.y;
    const int q0 = qt * 128;
    const int b = bh >> 4, h = bh & 15;

    const size_t bhoff = (size_t)bh * SEQC * 64;
    const __half *Q = QKV + bhoff;
    const __half *K = QKV + QSZ + bhoff;
    const __half *V = QKV + 2 * QSZ + bhoff;

    auto fillkv = [&](int t, int buf) {
        uint32_t base = sb + QREGA + buf * STG;
#pragma unroll
        for (int i = 0; i < 2; i++) {
            int idx = tid + i * 256;           // 0..511
            int row = idx >> 3, c8 = idx & 7;
            uint32_t off = (uint32_t)row * AP + c8 * 16;
            size_t go = (size_t)(t * 64 + row) * 64 + c8 * 8;
            CP_ASYNC(base + 0 * KVARR + off, K + go);
            CP_ASYNC(base + 1 * KVARR + off, V + go);
        }
        CP_COMMIT();
    };

    fillkv(0, 0);
    // Q tile: 128 rows x 8 chunks = 1024, 4 per thread
#pragma unroll
    for (int i = 0; i < 4; i++) {
        int idx = tid + i * 256;
        int row = idx >> 3, c8 = idx & 7;
        uint32_t off = (uint32_t)row * AP + c8 * 16;
        *(uint4*)(smc + off) = *(const uint4*)(Q + (size_t)(q0 + row) * 64 + c8 * 8);
    }
    __syncthreads();

    uint32_t qh[4][4];
    {
        const int arow = w * 16 + (lane & 15);
#pragma unroll
        for (int s = 0; s < 4; s++) {
            uint32_t off = (uint32_t)arow * AP + (s * 16 + (lane >> 4) * 8) * 2;
            ldsm4(qh[s][0], qh[s][1], qh[s][2], qh[s][3], sb + off);
        }
    }

    float o[8][4];
#pragma unroll
    for (int j = 0; j < 8; j++)
#pragma unroll
        for (int e = 0; e < 4; e++) o[j][e] = 0.f;
    float m_lo = -1e30f, m_hi = -1e30f, l_lo = 0.f, l_hi = 0.f;

    const int rlo = q0 + w * 16 + (lane >> 2);
    const int rhi = rlo + 8;
    const int g = lane >> 3;
    const int tmax = 2 * qt + 1;

    for (int t = 0; t <= tmax; t++) {
        if (t + 1 <= tmax) { fillkv(t + 1, (t + 1) & 1); CP_WAIT(1); }
        else               { CP_WAIT(0); }
        __syncthreads();

        const uint32_t bbase = sb + QREGA + (uint32_t)(t & 1) * STG;
        const uint32_t Ko = bbase, Vo = bbase + KVARR;

        float s_[8][4];
#pragma unroll
        for (int j = 0; j < 8; j++)
#pragma unroll
            for (int e = 0; e < 4; e++) s_[j][e] = 0.f;

        // S = Q K^T (single fp16 pass)
#pragma unroll
        for (int s = 0; s < 4; s++) {
            const int brow = (g >> 1) * 8 + (lane & 7);
            const int bcol = s * 16 + (g & 1) * 8;
            uint32_t kh[4][4];
#pragma unroll
            for (int p = 0; p < 4; p++) {
                uint32_t off = (uint32_t)(brow + p * 16) * AP + bcol * 2;
                ldsm4(kh[p][0], kh[p][1], kh[p][2], kh[p][3], Ko + off);
            }
#pragma unroll
            for (int p = 0; p < 4; p++) {
                mmah(s_[2 * p],     qh[s], &kh[p][0]);
                mmah(s_[2 * p + 1], qh[s], &kh[p][2]);
            }
        }

        const bool msk = (t >= 2 * qt);
#pragma unroll
        for (int j = 0; j < 8; j++) {
            int c = t * 64 + j * 8 + (lane & 3) * 2;
#pragma unroll
            for (int e = 0; e < 4; e++) s_[j][e] *= 0.125f;
            if (msk) {
                if (c > rlo)     s_[j][0] = -1e30f;
                if (c + 1 > rlo) s_[j][1] = -1e30f;
                if (c > rhi)     s_[j][2] = -1e30f;
                if (c + 1 > rhi) s_[j][3] = -1e30f;
            }
        }

        float rm_lo = -1e30f, rm_hi = -1e30f;
#pragma unroll
        for (int j = 0; j < 8; j++) {
            rm_lo = fmaxf(rm_lo, fmaxf(s_[j][0], s_[j][1]));
            rm_hi = fmaxf(rm_hi, fmaxf(s_[j][2], s_[j][3]));
        }
        rm_lo = fmaxf(rm_lo, __shfl_xor_sync(0xffffffffu, rm_lo, 1));
        rm_lo = fmaxf(rm_lo, __shfl_xor_sync(0xffffffffu, rm_lo, 2));
        rm_hi = fmaxf(rm_hi, __shfl_xor_sync(0xffffffffu, rm_hi, 1));
        rm_hi = fmaxf(rm_hi, __shfl_xor_sync(0xffffffffu, rm_hi, 2));
        float mn_lo = fmaxf(m_lo, rm_lo), mn_hi = fmaxf(m_hi, rm_hi);
        float cor_lo = __expf(m_lo - mn_lo), cor_hi = __expf(m_hi - mn_hi);
        m_lo = mn_lo; m_hi = mn_hi;
        float sum_lo = 0.f, sum_hi = 0.f;
#pragma unroll
        for (int j = 0; j < 8; j++) {
            s_[j][0] = __expf(s_[j][0] - mn_lo); sum_lo += s_[j][0];
            s_[j][1] = __expf(s_[j][1] - mn_lo); sum_lo += s_[j][1];
            s_[j][2] = __expf(s_[j][2] - mn_hi); sum_hi += s_[j][2];
            s_[j][3] = __expf(s_[j][3] - mn_hi); sum_hi += s_[j][3];
        }
        sum_lo += __shfl_xor_sync(0xffffffffu, sum_lo, 1);
        sum_lo += __shfl_xor_sync(0xffffffffu, sum_lo, 2);
        sum_hi += __shfl_xor_sync(0xffffffffu, sum_hi, 1);
        sum_hi += __shfl_xor_sync(0xffffffffu, sum_hi, 2);
        l_lo = l_lo * cor_lo + sum_lo;
        l_hi = l_hi * cor_hi + sum_hi;
#pragma unroll
        for (int j = 0; j < 8; j++) {
            o[j][0] *= cor_lo; o[j][1] *= cor_lo;
            o[j][2] *= cor_hi; o[j][3] *= cor_hi;
        }

        // O += P V (single fp16 pass; P packed in-register)
#pragma unroll
        for (int s = 0; s < 4; s++) {
            uint32_t ph[4];
            ph[0] = pk2h(s_[2 * s][0],     s_[2 * s][1]);
            ph[1] = pk2h(s_[2 * s][2],     s_[2 * s][3]);
            ph[2] = pk2h(s_[2 * s + 1][0], s_[2 * s + 1][1]);
            ph[3] = pk2h(s_[2 * s + 1][2], s_[2 * s + 1][3]);
            const int kvr = s * 16 + (g & 1) * 8 + (lane & 7);
            uint32_t vh[4][4];
#pragma unroll
            for (int p = 0; p < 4; p++) {
                uint32_t off = (uint32_t)kvr * AP + ((g >> 1) * 8 + p * 16) * 2;
                ldsm4t(vh[p][0], vh[p][1], vh[p][2], vh[p][3], Vo + off);
            }
#pragma unroll
            for (int p = 0; p < 4; p++) {
                mmah(o[2 * p],     ph, &vh[p][0]);
                mmah(o[2 * p + 1], ph, &vh[p][2]);
            }
        }
        __syncthreads();   // buffer (t&1) free for refill at iter t+1
    }

    const float il_lo = 1.f / l_lo, il_hi = 1.f / l_hi;
    const int colb = h * 64 + (lane & 3) * 2;
#pragma unroll
    for (int j = 0; j < 8; j++) {
        int col = colb + j * 8;
        size_t ilo = ((size_t)(b * SEQC + rlo) * DMOD + col);
        size_t ihi = ((size_t)(b * SEQC + rhi) * DMOD + col);
        uint32_t h32, l32;
        split2(o[j][0] * il_lo, o[j][1] * il_lo, h32, l32);
        AOh[ilo >> 1] = h32; AOl[ilo >> 1] = l32;
        split2(o[j][2] * il_hi, o[j][3] * il_hi, h32, l32);
        AOh[ihi >> 1] = h32; AOl[ihi >> 1] = l32;
    }
}

// ------------------------------ launch --------------------------------------
extern "C" void kernel_launch(void* const* d_in, const int* in_sizes, int n_in,
                              void* d_out, int out_size) {
    const float* x = (const float*)d_in[0];
    float* out = (float*)d_out;

    __nv_bfloat16 *xh, *xl, *wh, *wl, *aoh, *aol;
    __half* qkv;
    cudaGetSymbolAddress((void**)&xh, g_xh);
    cudaGetSymbolAddress((void**)&xl, g_xl);
    cudaGetSymbolAddress((void**)&wh, g_wh);
    cudaGetSymbolAddress((void**)&wl, g_wl);
    cudaGetSymbolAddress((void**)&qkv, g_qkv);
    cudaGetSymbolAddress((void**)&aoh, g_aoh);
    cudaGetSymbolAddress((void**)&aol, g_aol);

    const int NW = DMOD * DMOD;

    split_all<<<(N4X + 4 * N4W + 255) / 256, 256>>>(
        (const float4*)x, (const float4*)d_in[1], (const float4*)d_in[2],
        (const float4*)d_in[3], (const float4*)d_in[4],
        (uint2*)xh, (uint2*)xl, (uint2*)wh, (uint2*)wl);

    const int gshm = 2 * BUF;   // 81920
    cudaFuncSetAttribute(gemm_bf<1>, cudaFuncAttributeMaxDynamicSharedMemorySize, gshm);
    cudaFuncSetAttribute(gemm_bf<0>, cudaFuncAttributeMaxDynamicSharedMemorySize, gshm);

    // fused QKV projection: N = 3072, fp16 output
    gemm_bf<1><<<dim3(24, 64), 256, gshm>>>(xh, xl, wh, wl, nullptr, (uint32_t*)qkv);

    const int ashm = QREGA + 2 * STG;   // 55296
    cudaFuncSetAttribute(attn_mma, cudaFuncAttributeMaxDynamicSharedMemorySize, ashm);
    attn_mma<<<dim3(SEQC / 128, BATCHC * NHEAD), 256, ashm>>>(qkv,
                                                              (uint32_t*)aoh,
                                                              (uint32_t*)aol);

    gemm_bf<0><<<dim3(8, 64), 256, gshm>>>(aoh, aol, wh + (size_t)3 * NW,
                                           wl + (size_t)3 * NW, out, nullptr);
}

// round 13
// speedup vs baseline: 2.2530x; 1.7251x over previous
#include <cuda_runtime.h>
#include <cuda_fp16.h>
#include <cstdint>

#define SEQC 2048
#define BATCHC 4
#define NHEAD 16
#define DMOD 1024
#define MTOT (BATCHC * SEQC)     // 8192
#define QSZ (MTOT * DMOD)        // 8388608 elems per Q/K/V tensor

__device__ __half g_xf[MTOT * DMOD];
__device__ __half g_wf[4 * DMOD * DMOD];
__device__ __half g_qkv[3 * QSZ];
__device__ __half g_ao[MTOT * DMOD];

// ------------------------------ helpers -------------------------------------
__device__ __forceinline__ uint32_t su32(const void* p) {
    uint32_t a;
    asm("{ .reg .u64 t; cvta.to.shared.u64 t, %1; cvt.u32.u64 %0, t; }" : "=r"(a) : "l"(p));
    return a;
}
__device__ __forceinline__ uint32_t pk2h(float e0, float e1) {      // f16x2
    uint32_t d;
    asm("cvt.rn.f16x2.f32 %0, %1, %2;" : "=r"(d) : "f"(e1), "f"(e0));
    return d;
}
__device__ __forceinline__ void ldsm4(uint32_t& r0, uint32_t& r1, uint32_t& r2,
                                      uint32_t& r3, uint32_t a) {
    asm volatile("ldmatrix.sync.aligned.m8n8.x4.shared.b16 {%0,%1,%2,%3}, [%4];"
                 : "=r"(r0), "=r"(r1), "=r"(r2), "=r"(r3) : "r"(a));
}
__device__ __forceinline__ void ldsm4t(uint32_t& r0, uint32_t& r1, uint32_t& r2,
                                       uint32_t& r3, uint32_t a) {
    asm volatile("ldmatrix.sync.aligned.m8n8.x4.trans.shared.b16 {%0,%1,%2,%3}, [%4];"
                 : "=r"(r0), "=r"(r1), "=r"(r2), "=r"(r3) : "r"(a));
}
__device__ __forceinline__ void mmah(float* c, const uint32_t* a, const uint32_t* b) {
    asm volatile(
        "mma.sync.aligned.m16n8k16.row.col.f32.f16.f16.f32 "
        "{%0,%1,%2,%3},{%4,%5,%6,%7},{%8,%9},{%0,%1,%2,%3};"
        : "+f"(c[0]), "+f"(c[1]), "+f"(c[2]), "+f"(c[3])
        : "r"(a[0]), "r"(a[1]), "r"(a[2]), "r"(a[3]), "r"(b[0]), "r"(b[1]));
}
#define CP_ASYNC(dst, src) \
    asm volatile("cp.async.ca.shared.global [%0], [%1], 16;" :: "r"(dst), "l"(src) : "memory")
#define CP_COMMIT() asm volatile("cp.async.commit_group;" ::: "memory")
#define CP_WAIT(n)  asm volatile("cp.async.wait_group %0;" :: "n"(n) : "memory")

// --------------- fp32 -> fp16 convert, ALL tensors in one launch -------------
#define N4X (MTOT * DMOD / 4)
#define N4W (DMOD * DMOD / 4)

__global__ void split_all(const float4* __restrict__ x,
                          const float4* __restrict__ w0, const float4* __restrict__ w1,
                          const float4* __restrict__ w2, const float4* __restrict__ w3,
                          uint2* __restrict__ xf, uint2* __restrict__ wf) {
    int i = blockIdx.x * blockDim.x + threadIdx.x;
    const float4* src;
    uint2* dst;
    int off;
    if (i < N4X) {
        src = x; dst = xf; off = i;
    } else {
        int j = i - N4X;
        int wsel = j >> 18;
        off = j & (N4W - 1);
        src = (wsel == 0) ? w0 : (wsel == 1) ? w1 : (wsel == 2) ? w2 : w3;
        dst = wf + (size_t)wsel * N4W;
    }
    float4 v = src[off];
    dst[off] = make_uint2(pk2h(v.x, v.y), pk2h(v.z, v.w));
}

// ---------- GEMM: C[M,N] = A[M,1024] B[N,1024]^T, fp16 single-pass -----------
#define GPB 80
#define ARR (128 * GPB)          // 10240 per array
#define BUF (2 * ARR)            // 20480 per stage

template <int MODE>                  // 1: fp16 QKV out (headsplit), 0: fp32 out
__global__ __launch_bounds__(256, 2) void gemm_h(const __half* __restrict__ A,
                                                 const __half* __restrict__ B,
                                                 float* __restrict__ C,
                                                 uint32_t* __restrict__ Oh) {
    extern __shared__ char sm[];
    const uint32_t sb = su32(sm);
    const int tid = threadIdx.x, lane = tid & 31, wid = tid >> 5;
    const int m0 = blockIdx.y * 128, n0 = blockIdx.x * 128;
    const int wm = (wid >> 2) * 64, wn = (wid & 3) * 32;

    auto fill = [&](int kb, int buf) {
        uint32_t base = sb + buf * BUF;
#pragma unroll
        for (int i = 0; i < 2; i++) {
            int idx = tid + i * 256;           // 0..511
            int row = idx >> 2, c4 = idx & 3;
            uint32_t off = (uint32_t)row * GPB + c4 * 16;
            CP_ASYNC(base + 0 * ARR + off, A + (size_t)(m0 + row) * 1024 + kb + c4 * 8);
            CP_ASYNC(base + 1 * ARR + off, B + (size_t)(n0 + row) * 1024 + kb + c4 * 8);
        }
        CP_COMMIT();
    };

    float acc[4][4][4];
#pragma unroll
    for (int i = 0; i < 4; i++)
#pragma unroll
        for (int j = 0; j < 4; j++)
#pragma unroll
            for (int e = 0; e < 4; e++) acc[i][j][e] = 0.f;

    fill(0, 0);
    for (int t = 0; t < 32; t++) {
        if (t + 1 < 32) { fill((t + 1) * 32, (t + 1) & 1); CP_WAIT(1); }
        else            { CP_WAIT(0); }
        __syncthreads();

        const uint32_t bb = sb + (t & 1) * BUF;
#pragma unroll
        for (int s = 0; s < 2; s++) {
            uint32_t ah[4][4];
            const int arow = wm + (lane & 15);
            const int acol = s * 16 + (lane >> 4) * 8;
#pragma unroll
            for (int i = 0; i < 4; i++) {
                uint32_t off = (uint32_t)(arow + i * 16) * GPB + acol * 2;
                ldsm4(ah[i][0], ah[i][1], ah[i][2], ah[i][3], bb + 0 * ARR + off);
            }
            const int g = lane >> 3;
            const int brow = wn + (g >> 1) * 8 + (lane & 7);
            const int bcol = s * 16 + (g & 1) * 8;
#pragma unroll
            for (int p = 0; p < 2; p++) {
                uint32_t bh[4];
                uint32_t off = (uint32_t)(brow + p * 16) * GPB + bcol * 2;
                ldsm4(bh[0], bh[1], bh[2], bh[3], bb + 1 * ARR + off);
#pragma unroll
                for (int i = 0; i < 4; i++) mmah(acc[i][2 * p],     ah[i], &bh[0]);
#pragma unroll
                for (int i = 0; i < 4; i++) mmah(acc[i][2 * p + 1], ah[i], &bh[2]);
            }
        }
        __syncthreads();
    }

    const int r0 = m0 + wm + (lane >> 2);
    const int cb = n0 + wn + (lane & 3) * 2;
#pragma unroll
    for (int i = 0; i < 4; i++) {
#pragma unroll
        for (int half = 0; half < 2; half++) {
            int r = r0 + i * 16 + half * 8;
#pragma unroll
            for (int j = 0; j < 4; j++) {
                int c = cb + j * 8;
                float e0 = half ? acc[i][j][2] : acc[i][j][0];
                float e1 = half ? acc[i][j][3] : acc[i][j][1];
                if (MODE == 1) {
                    int which = c >> 10, cc = c & 1023;
                    int h = cc >> 6, dk = cc & 63;
                    int b = r >> 11, sdx = r & 2047;
                    size_t idx = (size_t)which * QSZ +
                                 ((((size_t)b * NHEAD + h) * SEQC + sdx) << 6) + dk;
                    Oh[idx >> 1] = pk2h(e0, e1);
                } else {
                    *(float2*)&C[(size_t)r * 1024 + c] = make_float2(e0, e1);
                }
            }
        }
    }
}

// ------------------ flash attention, fp16 single-pass mma, causal ------------
#define AP 144
#define KVARR (64 * AP)          // 9216 per K or V array
#define STG (2 * KVARR)          // 18432 per KV stage
#define QREGA (128 * AP)         // 18432 fp16 Q tile

__global__ void attn_mma(const __half* __restrict__ QKV,
                         uint32_t* __restrict__ AO) {
    extern __shared__ char smc[];
    const uint32_t sb = su32(smc);
    const int tid = threadIdx.x, lane = tid & 31, w = tid >> 5;
    const int qt = blockIdx.x, bh = blockIdx.y;
    const int q0 = qt * 128;
    const int b = bh >> 4, h = bh & 15;

    const size_t bhoff = (size_t)bh * SEQC * 64;
    const __half *Q = QKV + bhoff;
    const __half *K = QKV + QSZ + bhoff;
    const __half *V = QKV + 2 * QSZ + bhoff;

    auto fillkv = [&](int t, int buf) {
        uint32_t base = sb + QREGA + buf * STG;
#pragma unroll
        for (int i = 0; i < 2; i++) {
            int idx = tid + i * 256;
            int row = idx >> 3, c8 = idx & 7;
            uint32_t off = (uint32_t)row * AP + c8 * 16;
            size_t go = (size_t)(t * 64 + row) * 64 + c8 * 8;
            CP_ASYNC(base + 0 * KVARR + off, K + go);
            CP_ASYNC(base + 1 * KVARR + off, V + go);
        }
        CP_COMMIT();
    };

    fillkv(0, 0);
#pragma unroll
    for (int i = 0; i < 4; i++) {
        int idx = tid + i * 256;
        int row = idx >> 3, c8 = idx & 7;
        uint32_t off = (uint32_t)row * AP + c8 * 16;
        *(uint4*)(smc + off) = *(const uint4*)(Q + (size_t)(q0 + row) * 64 + c8 * 8);
    }
    __syncthreads();

    uint32_t qh[4][4];
    {
        const int arow = w * 16 + (lane & 15);
#pragma unroll
        for (int s = 0; s < 4; s++) {
            uint32_t off = (uint32_t)arow * AP + (s * 16 + (lane >> 4) * 8) * 2;
            ldsm4(qh[s][0], qh[s][1], qh[s][2], qh[s][3], sb + off);
        }
    }

    float o[8][4];
#pragma unroll
    for (int j = 0; j < 8; j++)
#pragma unroll
        for (int e = 0; e < 4; e++) o[j][e] = 0.f;
    float m_lo = -1e30f, m_hi = -1e30f, l_lo = 0.f, l_hi = 0.f;

    const int rlo = q0 + w * 16 + (lane >> 2);
    const int rhi = rlo + 8;
    const int g = lane >> 3;
    const int tmax = 2 * qt + 1;

    for (int t = 0; t <= tmax; t++) {
        if (t + 1 <= tmax) { fillkv(t + 1, (t + 1) & 1); CP_WAIT(1); }
        else               { CP_WAIT(0); }
        __syncthreads();

        const uint32_t bbase = sb + QREGA + (uint32_t)(t & 1) * STG;
        const uint32_t Ko = bbase, Vo = bbase + KVARR;

        float s_[8][4];
#pragma unroll
        for (int j = 0; j < 8; j++)
#pragma unroll
            for (int e = 0; e < 4; e++) s_[j][e] = 0.f;

#pragma unroll
        for (int s = 0; s < 4; s++) {
            const int brow = (g >> 1) * 8 + (lane & 7);
            const int bcol = s * 16 + (g & 1) * 8;
            uint32_t kh[4][4];
#pragma unroll
            for (int p = 0; p < 4; p++) {
                uint32_t off = (uint32_t)(brow + p * 16) * AP + bcol * 2;
                ldsm4(kh[p][0], kh[p][1], kh[p][2], kh[p][3], Ko + off);
            }
#pragma unroll
            for (int p = 0; p < 4; p++) {
                mmah(s_[2 * p],     qh[s], &kh[p][0]);
                mmah(s_[2 * p + 1], qh[s], &kh[p][2]);
            }
        }

        const bool msk = (t >= 2 * qt);
#pragma unroll
        for (int j = 0; j < 8; j++) {
            int c = t * 64 + j * 8 + (lane & 3) * 2;
#pragma unroll
            for (int e = 0; e < 4; e++) s_[j][e] *= 0.125f;
            if (msk) {
                if (c > rlo)     s_[j][0] = -1e30f;
                if (c + 1 > rlo) s_[j][1] = -1e30f;
                if (c > rhi)     s_[j][2] = -1e30f;
                if (c + 1 > rhi) s_[j][3] = -1e30f;
            }
        }

        float rm_lo = -1e30f, rm_hi = -1e30f;
#pragma unroll
        for (int j = 0; j < 8; j++) {
            rm_lo = fmaxf(rm_lo, fmaxf(s_[j][0], s_[j][1]));
            rm_hi = fmaxf(rm_hi, fmaxf(s_[j][2], s_[j][3]));
        }
        rm_lo = fmaxf(rm_lo, __shfl_xor_sync(0xffffffffu, rm_lo, 1));
        rm_lo = fmaxf(rm_lo, __shfl_xor_sync(0xffffffffu, rm_lo, 2));
        rm_hi = fmaxf(rm_hi, __shfl_xor_sync(0xffffffffu, rm_hi, 1));
        rm_hi = fmaxf(rm_hi, __shfl_xor_sync(0xffffffffu, rm_hi, 2));
        float mn_lo = fmaxf(m_lo, rm_lo), mn_hi = fmaxf(m_hi, rm_hi);
        float cor_lo = __expf(m_lo - mn_lo), cor_hi = __expf(m_hi - mn_hi);
        m_lo = mn_lo; m_hi = mn_hi;
        float sum_lo = 0.f, sum_hi = 0.f;
#pragma unroll
        for (int j = 0; j < 8; j++) {
            s_[j][0] = __expf(s_[j][0] - mn_lo); sum_lo += s_[j][0];
            s_[j][1] = __expf(s_[j][1] - mn_lo); sum_lo += s_[j][1];
            s_[j][2] = __expf(s_[j][2] - mn_hi); sum_hi += s_[j][2];
            s_[j][3] = __expf(s_[j][3] - mn_hi); sum_hi += s_[j][3];
        }
        sum_lo += __shfl_xor_sync(0xffffffffu, sum_lo, 1);
        sum_lo += __shfl_xor_sync(0xffffffffu, sum_lo, 2);
        sum_hi += __shfl_xor_sync(0xffffffffu, sum_hi, 1);
        sum_hi += __shfl_xor_sync(0xffffffffu, sum_hi, 2);
        l_lo = l_lo * cor_lo + sum_lo;
        l_hi = l_hi * cor_hi + sum_hi;
#pragma unroll
        for (int j = 0; j < 8; j++) {
            o[j][0] *= cor_lo; o[j][1] *= cor_lo;
            o[j][2] *= cor_hi; o[j][3] *= cor_hi;
        }

#pragma unroll
        for (int s = 0; s < 4; s++) {
            uint32_t ph[4];
            ph[0] = pk2h(s_[2 * s][0],     s_[2 * s][1]);
            ph[1] = pk2h(s_[2 * s][2],     s_[2 * s][3]);
            ph[2] = pk2h(s_[2 * s + 1][0], s_[2 * s + 1][1]);
            ph[3] = pk2h(s_[2 * s + 1][2], s_[2 * s + 1][3]);
            const int kvr = s * 16 + (g & 1) * 8 + (lane & 7);
            uint32_t vh[4][4];
#pragma unroll
            for (int p = 0; p < 4; p++) {
                uint32_t off = (uint32_t)kvr * AP + ((g >> 1) * 8 + p * 16) * 2;
                ldsm4t(vh[p][0], vh[p][1], vh[p][2], vh[p][3], Vo + off);
            }
#pragma unroll
            for (int p = 0; p < 4; p++) {
                mmah(o[2 * p],     ph, &vh[p][0]);
                mmah(o[2 * p + 1], ph, &vh[p][2]);
            }
        }
        __syncthreads();
    }

    const float il_lo = 1.f / l_lo, il_hi = 1.f / l_hi;
    const int colb = h * 64 + (lane & 3) * 2;
#pragma unroll
    for (int j = 0; j < 8; j++) {
        int col = colb + j * 8;
        size_t ilo = ((size_t)(b * SEQC + rlo) * DMOD + col);
        size_t ihi = ((size_t)(b * SEQC + rhi) * DMOD + col);
        AO[ilo >> 1] = pk2h(o[j][0] * il_lo, o[j][1] * il_lo);
        AO[ihi >> 1] = pk2h(o[j][2] * il_hi, o[j][3] * il_hi);
    }
}

// ------------------------------ launch --------------------------------------
extern "C" void kernel_launch(void* const* d_in, const int* in_sizes, int n_in,
                              void* d_out, int out_size) {
    const float* x = (const float*)d_in[0];
    float* out = (float*)d_out;

    __half *xf, *wf, *qkv, *ao;
    cudaGetSymbolAddress((void**)&xf, g_xf);
    cudaGetSymbolAddress((void**)&wf, g_wf);
    cudaGetSymbolAddress((void**)&qkv, g_qkv);
    cudaGetSymbolAddress((void**)&ao, g_ao);

    const int NW = DMOD * DMOD;

    split_all<<<(N4X + 4 * N4W + 255) / 256, 256>>>(
        (const float4*)x, (const float4*)d_in[1], (const float4*)d_in[2],
        (const float4*)d_in[3], (const float4*)d_in[4],
        (uint2*)xf, (uint2*)wf);

    const int gshm = 2 * BUF;   // 40960
    cudaFuncSetAttribute(gemm_h<1>, cudaFuncAttributeMaxDynamicSharedMemorySize, gshm);
    cudaFuncSetAttribute(gemm_h<0>, cudaFuncAttributeMaxDynamicSharedMemorySize, gshm);

    // fused QKV projection: N = 3072, fp16 output
    gemm_h<1><<<dim3(24, 64), 256, gshm>>>(xf, wf, nullptr, (uint32_t*)qkv);

    const int ashm = QREGA + 2 * STG;   // 55296
    cudaFuncSetAttribute(attn_mma, cudaFuncAttributeMaxDynamicSharedMemorySize, ashm);
    attn_mma<<<dim3(SEQC / 128, BATCHC * NHEAD), 256, ashm>>>(qkv, (uint32_t*)ao);

    gemm_h<0><<<dim3(8, 64), 256, gshm>>>(ao, wf + (size_t)3 * NW, out, nullptr);
}

// round 14
// speedup vs baseline: 2.5074x; 1.1130x over previous
#include <cuda_runtime.h>
#include <cuda_fp16.h>
#include <cstdint>

#define SEQC 2048
#define BATCHC 4
#define NHEAD 16
#define DMOD 1024
#define MTOT (BATCHC * SEQC)     // 8192
#define QSZ (MTOT * DMOD)        // 8388608 elems per Q/K/V tensor

__device__ __half g_xf[MTOT * DMOD];
__device__ __half g_wf[4 * DMOD * DMOD];
__device__ __half g_qkv[3 * QSZ];
__device__ __half g_ao[MTOT * DMOD];

// ------------------------------ helpers -------------------------------------
__device__ __forceinline__ uint32_t su32(const void* p) {
    uint32_t a;
    asm("{ .reg .u64 t; cvta.to.shared.u64 t, %1; cvt.u32.u64 %0, t; }" : "=r"(a) : "l"(p));
    return a;
}
__device__ __forceinline__ uint32_t pk2h(float e0, float e1) {      // f16x2
    uint32_t d;
    asm("cvt.rn.f16x2.f32 %0, %1, %2;" : "=r"(d) : "f"(e1), "f"(e0));
    return d;
}
__device__ __forceinline__ void ldsm4(uint32_t& r0, uint32_t& r1, uint32_t& r2,
                                      uint32_t& r3, uint32_t a) {
    asm volatile("ldmatrix.sync.aligned.m8n8.x4.shared.b16 {%0,%1,%2,%3}, [%4];"
                 : "=r"(r0), "=r"(r1), "=r"(r2), "=r"(r3) : "r"(a));
}
__device__ __forceinline__ void ldsm4t(uint32_t& r0, uint32_t& r1, uint32_t& r2,
                                       uint32_t& r3, uint32_t a) {
    asm volatile("ldmatrix.sync.aligned.m8n8.x4.trans.shared.b16 {%0,%1,%2,%3}, [%4];"
                 : "=r"(r0), "=r"(r1), "=r"(r2), "=r"(r3) : "r"(a));
}
__device__ __forceinline__ void mmah(float* c, const uint32_t* a, const uint32_t* b) {
    asm volatile(
        "mma.sync.aligned.m16n8k16.row.col.f32.f16.f16.f32 "
        "{%0,%1,%2,%3},{%4,%5,%6,%7},{%8,%9},{%0,%1,%2,%3};"
        : "+f"(c[0]), "+f"(c[1]), "+f"(c[2]), "+f"(c[3])
        : "r"(a[0]), "r"(a[1]), "r"(a[2]), "r"(a[3]), "r"(b[0]), "r"(b[1]));
}
#define CP_ASYNC(dst, src) \
    asm volatile("cp.async.cg.shared.global [%0], [%1], 16;" :: "r"(dst), "l"(src) : "memory")
#define CP_COMMIT() asm volatile("cp.async.commit_group;" ::: "memory")
#define CP_WAIT(n)  asm volatile("cp.async.wait_group %0;" :: "n"(n) : "memory")

// --------------- fp32 -> fp16 convert, ALL tensors in one launch -------------
#define N4X (MTOT * DMOD / 4)
#define N4W (DMOD * DMOD / 4)

__global__ void split_all(const float4* __restrict__ x,
                          const float4* __restrict__ w0, const float4* __restrict__ w1,
                          const float4* __restrict__ w2, const float4* __restrict__ w3,
                          uint2* __restrict__ xf, uint2* __restrict__ wf) {
    int i = blockIdx.x * blockDim.x + threadIdx.x;
    const float4* src;
    uint2* dst;
    int off;
    if (i < N4X) {
        src = x; dst = xf; off = i;
    } else {
        int j = i - N4X;
        int wsel = j >> 18;
        off = j & (N4W - 1);
        src = (wsel == 0) ? w0 : (wsel == 1) ? w1 : (wsel == 2) ? w2 : w3;
        dst = wf + (size_t)wsel * N4W;
    }
    float4 v = src[off];
    dst[off] = make_uint2(pk2h(v.x, v.y), pk2h(v.z, v.w));
}

// ---------- GEMM: C[M,N] = A[M,1024] B[N,1024]^T, fp16, BK=64 ----------------
#define GPB 144                   // 64 fp16 = 128B + 16B pad per row
#define ARR (128 * GPB)           // 18432 per array
#define BUF (2 * ARR)             // 36864 per stage

template <int MODE>                  // 1: fp16 QKV out (headsplit), 0: fp32 out
__global__ __launch_bounds__(256, 2) void gemm_h(const __half* __restrict__ A,
                                                 const __half* __restrict__ B,
                                                 float* __restrict__ C,
                                                 uint32_t* __restrict__ Oh) {
    extern __shared__ char sm[];
    const uint32_t sb = su32(sm);
    const int tid = threadIdx.x, lane = tid & 31, wid = tid >> 5;
    const int m0 = blockIdx.y * 128, n0 = blockIdx.x * 128;
    const int wm = (wid >> 2) * 64, wn = (wid & 3) * 32;

    auto fill = [&](int kb, int buf) {
        uint32_t base = sb + buf * BUF;
#pragma unroll
        for (int i = 0; i < 4; i++) {
            int idx = tid + i * 256;          // 0..1023
            int row = idx >> 3, c8 = idx & 7;
            uint32_t off = (uint32_t)row * GPB + c8 * 16;
            CP_ASYNC(base + 0 * ARR + off, A + (size_t)(m0 + row) * 1024 + kb + c8 * 8);
            CP_ASYNC(base + 1 * ARR + off, B + (size_t)(n0 + row) * 1024 + kb + c8 * 8);
        }
        CP_COMMIT();
    };

    float acc[4][4][4];
#pragma unroll
    for (int i = 0; i < 4; i++)
#pragma unroll
        for (int j = 0; j < 4; j++)
#pragma unroll
            for (int e = 0; e < 4; e++) acc[i][j][e] = 0.f;

    fill(0, 0);
    for (int t = 0; t < 16; t++) {
        if (t + 1 < 16) { fill((t + 1) * 64, (t + 1) & 1); CP_WAIT(1); }
        else            { CP_WAIT(0); }
        __syncthreads();

        const uint32_t bb = sb + (t & 1) * BUF;
#pragma unroll
        for (int s = 0; s < 4; s++) {
            uint32_t ah[4][4];
            const int arow = wm + (lane & 15);
            const int acol = s * 16 + (lane >> 4) * 8;
#pragma unroll
            for (int i = 0; i < 4; i++) {
                uint32_t off = (uint32_t)(arow + i * 16) * GPB + acol * 2;
                ldsm4(ah[i][0], ah[i][1], ah[i][2], ah[i][3], bb + 0 * ARR + off);
            }
            const int g = lane >> 3;
            const int brow = wn + (g >> 1) * 8 + (lane & 7);
            const int bcol = s * 16 + (g & 1) * 8;
#pragma unroll
            for (int p = 0; p < 2; p++) {
                uint32_t bh[4];
                uint32_t off = (uint32_t)(brow + p * 16) * GPB + bcol * 2;
                ldsm4(bh[0], bh[1], bh[2], bh[3], bb + 1 * ARR + off);
#pragma unroll
                for (int i = 0; i < 4; i++) mmah(acc[i][2 * p],     ah[i], &bh[0]);
#pragma unroll
                for (int i = 0; i < 4; i++) mmah(acc[i][2 * p + 1], ah[i], &bh[2]);
            }
        }
        __syncthreads();
    }

    const int r0 = m0 + wm + (lane >> 2);
    const int cb = n0 + wn + (lane & 3) * 2;
#pragma unroll
    for (int i = 0; i < 4; i++) {
#pragma unroll
        for (int half = 0; half < 2; half++) {
            int r = r0 + i * 16 + half * 8;
#pragma unroll
            for (int j = 0; j < 4; j++) {
                int c = cb + j * 8;
                float e0 = half ? acc[i][j][2] : acc[i][j][0];
                float e1 = half ? acc[i][j][3] : acc[i][j][1];
                if (MODE == 1) {
                    int which = c >> 10, cc = c & 1023;
                    int h = cc >> 6, dk = cc & 63;
                    int b = r >> 11, sdx = r & 2047;
                    size_t idx = (size_t)which * QSZ +
                                 ((((size_t)b * NHEAD + h) * SEQC + sdx) << 6) + dk;
                    Oh[idx >> 1] = pk2h(e0, e1);
                } else {
                    *(float2*)&C[(size_t)r * 1024 + c] = make_float2(e0, e1);
                }
            }
        }
    }
}

// ------------------ flash attention, fp16 single-pass mma, causal ------------
#define AP 144
#define KVARR (64 * AP)          // 9216 per K or V array
#define STG (2 * KVARR)          // 18432 per KV stage
#define QREGA (128 * AP)         // 18432 fp16 Q tile

__global__ void attn_mma(const __half* __restrict__ QKV,
                         uint32_t* __restrict__ AO) {
    extern __shared__ char smc[];
    const uint32_t sb = su32(smc);
    const int tid = threadIdx.x, lane = tid & 31, w = tid >> 5;
    const int qt = blockIdx.x, bh = blockIdx.y;
    const int q0 = qt * 128;
    const int b = bh >> 4, h = bh & 15;

    const size_t bhoff = (size_t)bh * SEQC * 64;
    const __half *Q = QKV + bhoff;
    const __half *K = QKV + QSZ + bhoff;
    const __half *V = QKV + 2 * QSZ + bhoff;

    auto fillkv = [&](int t, int buf) {
        uint32_t base = sb + QREGA + buf * STG;
#pragma unroll
        for (int i = 0; i < 2; i++) {
            int idx = tid + i * 256;
            int row = idx >> 3, c8 = idx & 7;
            uint32_t off = (uint32_t)row * AP + c8 * 16;
            size_t go = (size_t)(t * 64 + row) * 64 + c8 * 8;
            CP_ASYNC(base + 0 * KVARR + off, K + go);
            CP_ASYNC(base + 1 * KVARR + off, V + go);
        }
        CP_COMMIT();
    };

    fillkv(0, 0);
#pragma unroll
    for (int i = 0; i < 4; i++) {
        int idx = tid + i * 256;
        int row = idx >> 3, c8 = idx & 7;
        uint32_t off = (uint32_t)row * AP + c8 * 16;
        *(uint4*)(smc + off) = *(const uint4*)(Q + (size_t)(q0 + row) * 64 + c8 * 8);
    }
    __syncthreads();

    uint32_t qh[4][4];
    {
        const int arow = w * 16 + (lane & 15);
#pragma unroll
        for (int s = 0; s < 4; s++) {
            uint32_t off = (uint32_t)arow * AP + (s * 16 + (lane >> 4) * 8) * 2;
            ldsm4(qh[s][0], qh[s][1], qh[s][2], qh[s][3], sb + off);
        }
    }

    float o[8][4];
#pragma unroll
    for (int j = 0; j < 8; j++)
#pragma unroll
        for (int e = 0; e < 4; e++) o[j][e] = 0.f;
    float m_lo = -1e30f, m_hi = -1e30f, l_lo = 0.f, l_hi = 0.f;

    const int rlo = q0 + w * 16 + (lane >> 2);
    const int rhi = rlo + 8;
    const int g = lane >> 3;
    const int tmax = 2 * qt + 1;

    for (int t = 0; t <= tmax; t++) {
        if (t + 1 <= tmax) { fillkv(t + 1, (t + 1) & 1); CP_WAIT(1); }
        else               { CP_WAIT(0); }
        __syncthreads();

        const uint32_t bbase = sb + QREGA + (uint32_t)(t & 1) * STG;
        const uint32_t Ko = bbase, Vo = bbase + KVARR;

        float s_[8][4];
#pragma unroll
        for (int j = 0; j < 8; j++)
#pragma unroll
            for (int e = 0; e < 4; e++) s_[j][e] = 0.f;

#pragma unroll
        for (int s = 0; s < 4; s++) {
            const int brow = (g >> 1) * 8 + (lane & 7);
            const int bcol = s * 16 + (g & 1) * 8;
            uint32_t kh[4][4];
#pragma unroll
            for (int p = 0; p < 4; p++) {
                uint32_t off = (uint32_t)(brow + p * 16) * AP + bcol * 2;
                ldsm4(kh[p][0], kh[p][1], kh[p][2], kh[p][3], Ko + off);
            }
#pragma unroll
            for (int p = 0; p < 4; p++) {
                mmah(s_[2 * p],     qh[s], &kh[p][0]);
                mmah(s_[2 * p + 1], qh[s], &kh[p][2]);
            }
        }

        const bool msk = (t >= 2 * qt);
#pragma unroll
        for (int j = 0; j < 8; j++) {
            int c = t * 64 + j * 8 + (lane & 3) * 2;
#pragma unroll
            for (int e = 0; e < 4; e++) s_[j][e] *= 0.125f;
            if (msk) {
                if (c > rlo)     s_[j][0] = -1e30f;
                if (c + 1 > rlo) s_[j][1] = -1e30f;
                if (c > rhi)     s_[j][2] = -1e30f;
                if (c + 1 > rhi) s_[j][3] = -1e30f;
            }
        }

        float rm_lo = -1e30f, rm_hi = -1e30f;
#pragma unroll
        for (int j = 0; j < 8; j++) {
            rm_lo = fmaxf(rm_lo, fmaxf(s_[j][0], s_[j][1]));
            rm_hi = fmaxf(rm_hi, fmaxf(s_[j][2], s_[j][3]));
        }
        rm_lo = fmaxf(rm_lo, __shfl_xor_sync(0xffffffffu, rm_lo, 1));
        rm_lo = fmaxf(rm_lo, __shfl_xor_sync(0xffffffffu, rm_lo, 2));
        rm_hi = fmaxf(rm_hi, __shfl_xor_sync(0xffffffffu, rm_hi, 1));
        rm_hi = fmaxf(rm_hi, __shfl_xor_sync(0xffffffffu, rm_hi, 2));
        float mn_lo = fmaxf(m_lo, rm_lo), mn_hi = fmaxf(m_hi, rm_hi);
        float cor_lo = __expf(m_lo - mn_lo), cor_hi = __expf(m_hi - mn_hi);
        m_lo = mn_lo; m_hi = mn_hi;
        float sum_lo = 0.f, sum_hi = 0.f;
#pragma unroll
        for (int j = 0; j < 8; j++) {
            s_[j][0] = __expf(s_[j][0] - mn_lo); sum_lo += s_[j][0];
            s_[j][1] = __expf(s_[j][1] - mn_lo); sum_lo += s_[j][1];
            s_[j][2] = __expf(s_[j][2] - mn_hi); sum_hi += s_[j][2];
            s_[j][3] = __expf(s_[j][3] - mn_hi); sum_hi += s_[j][3];
        }
        sum_lo += __shfl_xor_sync(0xffffffffu, sum_lo, 1);
        sum_lo += __shfl_xor_sync(0xffffffffu, sum_lo, 2);
        sum_hi += __shfl_xor_sync(0xffffffffu, sum_hi, 1);
        sum_hi += __shfl_xor_sync(0xffffffffu, sum_hi, 2);
        l_lo = l_lo * cor_lo + sum_lo;
        l_hi = l_hi * cor_hi + sum_hi;
#pragma unroll
        for (int j = 0; j < 8; j++) {
            o[j][0] *= cor_lo; o[j][1] *= cor_lo;
            o[j][2] *= cor_hi; o[j][3] *= cor_hi;
        }

#pragma unroll
        for (int s = 0; s < 4; s++) {
            uint32_t ph[4];
            ph[0] = pk2h(s_[2 * s][0],     s_[2 * s][1]);
            ph[1] = pk2h(s_[2 * s][2],     s_[2 * s][3]);
            ph[2] = pk2h(s_[2 * s + 1][0], s_[2 * s + 1][1]);
            ph[3] = pk2h(s_[2 * s + 1][2], s_[2 * s + 1][3]);
            const int kvr = s * 16 + (g & 1) * 8 + (lane & 7);
            uint32_t vh[4][4];
#pragma unroll
            for (int p = 0; p < 4; p++) {
                uint32_t off = (uint32_t)kvr * AP + ((g >> 1) * 8 + p * 16) * 2;
                ldsm4t(vh[p][0], vh[p][1], vh[p][2], vh[p][3], Vo + off);
            }
#pragma unroll
            for (int p = 0; p < 4; p++) {
                mmah(o[2 * p],     ph, &vh[p][0]);
                mmah(o[2 * p + 1], ph, &vh[p][2]);
            }
        }
        __syncthreads();
    }

    const float il_lo = 1.f / l_lo, il_hi = 1.f / l_hi;
    const int colb = h * 64 + (lane & 3) * 2;
#pragma unroll
    for (int j = 0; j < 8; j++) {
        int col = colb + j * 8;
        size_t ilo = ((size_t)(b * SEQC + rlo) * DMOD + col);
        size_t ihi = ((size_t)(b * SEQC + rhi) * DMOD + col);
        AO[ilo >> 1] = pk2h(o[j][0] * il_lo, o[j][1] * il_lo);
        AO[ihi >> 1] = pk2h(o[j][2] * il_hi, o[j][3] * il_hi);
    }
}

// ------------------------------ launch --------------------------------------
extern "C" void kernel_launch(void* const* d_in, const int* in_sizes, int n_in,
                              void* d_out, int out_size) {
    const float* x = (const float*)d_in[0];
    float* out = (float*)d_out;

    __half *xf, *wf, *qkv, *ao;
    cudaGetSymbolAddress((void**)&xf, g_xf);
    cudaGetSymbolAddress((void**)&wf, g_wf);
    cudaGetSymbolAddress((void**)&qkv, g_qkv);
    cudaGetSymbolAddress((void**)&ao, g_ao);

    const int NW = DMOD * DMOD;

    split_all<<<(N4X + 4 * N4W + 255) / 256, 256>>>(
        (const float4*)x, (const float4*)d_in[1], (const float4*)d_in[2],
        (const float4*)d_in[3], (const float4*)d_in[4],
        (uint2*)xf, (uint2*)wf);

    const int gshm = 2 * BUF;   // 73728
    cudaFuncSetAttribute(gemm_h<1>, cudaFuncAttributeMaxDynamicSharedMemorySize, gshm);
    cudaFuncSetAttribute(gemm_h<0>, cudaFuncAttributeMaxDynamicSharedMemorySize, gshm);

    // fused QKV projection: N = 3072, fp16 output
    gemm_h<1><<<dim3(24, 64), 256, gshm>>>(xf, wf, nullptr, (uint32_t*)qkv);

    const int ashm = QREGA + 2 * STG;   // 55296
    cudaFuncSetAttribute(attn_mma, cudaFuncAttributeMaxDynamicSharedMemorySize, ashm);
    attn_mma<<<dim3(SEQC / 128, BATCHC * NHEAD), 256, ashm>>>(qkv, (uint32_t*)ao);

    gemm_h<0><<<dim3(8, 64), 256, gshm>>>(ao, wf + (size_t)3 * NW, out, nullptr);
}